// round 7
// baseline (speedup 1.0000x reference)
#include <cuda_runtime.h>
#include <math_constants.h>
#include <cstdint>

#define BSZ   2
#define TSEQ  2048
#define CDIM  1024
#define HN    16
#define DH    64

typedef unsigned long long ull;

// Scratch (allocation-free rule: __device__ globals)
__device__ float g_Q[(size_t)BSZ*HN*TSEQ*DH];   // [B,H,T,D]
__device__ float g_K[(size_t)BSZ*HN*TSEQ*DH];
__device__ float g_V[(size_t)BSZ*HN*TSEQ*DH];
__device__ float g_att[(size_t)BSZ*TSEQ*CDIM];  // [B,T,C]

// ---------------------------------------------------------------------------
// helpers
// ---------------------------------------------------------------------------
__device__ __forceinline__ float fast_exp2(float x) {
    float y;
    asm("ex2.approx.f32 %0, %1;" : "=f"(y) : "f"(x));
    return y;
}

__device__ __forceinline__ float to_tf32(float x) {
    float r;
    asm("cvt.rna.tf32.f32 %0, %1;" : "=f"(r) : "f"(x));
    return r;
}

// packed fp32x2 (Blackwell, plain-sm_103 legal)
__device__ __forceinline__ ull pack2(float x) {
    ull r; uint32_t u = __float_as_uint(x);
    asm("mov.b64 %0, {%1, %1};" : "=l"(r) : "r"(u));
    return r;
}
__device__ __forceinline__ ull fma2_(ull a, ull b, ull c) {
    ull d;
    asm("fma.rn.f32x2 %0, %1, %2, %3;" : "=l"(d) : "l"(a), "l"(b), "l"(c));
    return d;
}
__device__ __forceinline__ ull mul2_(ull a, ull b) {
    ull d;
    asm("mul.rn.f32x2 %0, %1, %2;" : "=l"(d) : "l"(a), "l"(b));
    return d;
}
__device__ __forceinline__ float2 unpack2(ull a) {
    uint32_t lo, hi;
    asm("mov.b64 {%0, %1}, %2;" : "=r"(lo), "=r"(hi) : "l"(a));
    float2 f; f.x = __uint_as_float(lo); f.y = __uint_as_float(hi);
    return f;
}

// tf32 mma.sync (sm_80+ legacy tensor path, compiles at compute_103)
__device__ __forceinline__ void mma_tf32(float* d, const uint32_t* a, const uint32_t* b)
{
    asm volatile(
        "mma.sync.aligned.m16n8k8.row.col.f32.tf32.tf32.f32 "
        "{%0,%1,%2,%3}, {%4,%5,%6,%7}, {%8,%9}, {%0,%1,%2,%3};"
        : "+f"(d[0]), "+f"(d[1]), "+f"(d[2]), "+f"(d[3])
        : "r"(a[0]), "r"(a[1]), "r"(a[2]), "r"(a[3]),
          "r"(b[0]), "r"(b[1]));
}

// ---------------------------------------------------------------------------
// tf32 tensor-core GEMM-NT: out[M,N] = A[M,K] @ W[N,K]^T + bias
// M = 4096, N = K = 1024.  CTA tile 128x128, 8 warps x (64x32), K-chunk 32.
// MODE 0: out row-major [M,N];  MODE 1: head-split [B,H,T,D]
// ---------------------------------------------------------------------------
#define GPAD 36   // 32 + 4 floats padding: conflict-free fragment gathers

template <int MODE>
__global__ __launch_bounds__(256)
void gemm_mma_kernel(const float* __restrict__ A,
                     const float* __restrict__ W,
                     const float* __restrict__ bias,
                     float* __restrict__ out)
{
    __shared__ float As[128][GPAD];
    __shared__ float Bs[128][GPAD];

    const int tid  = threadIdx.x;
    const int wid  = tid >> 5;
    const int lane = tid & 31;
    const int gID  = lane >> 2;      // 0..7
    const int tig  = lane & 3;       // 0..3
    const int n0 = blockIdx.x * 128;
    const int m0 = blockIdx.y * 128;
    const int wm = (wid >> 2) * 64;  // warp m-offset within tile
    const int wn = (wid & 3) * 32;   // warp n-offset within tile

    float acc[4][4][4];              // [mt][nt][reg]
#pragma unroll
    for (int mt = 0; mt < 4; ++mt)
#pragma unroll
        for (int nt = 0; nt < 4; ++nt)
#pragma unroll
            for (int r = 0; r < 4; ++r) acc[mt][nt][r] = 0.f;

    for (int k0 = 0; k0 < CDIM; k0 += 32) {
        // ---- stage 128x32 of A and of W into smem, rounding to tf32
#pragma unroll
        for (int i = 0; i < 4; ++i) {
            const int idx = tid + i * 256;       // 0..1023 float4 slots
            const int row = idx >> 3;            // 0..127
            const int q4  = (idx & 7) * 4;       // 0..28
            float4 a = *(const float4*)&A[(size_t)(m0 + row) * CDIM + k0 + q4];
            float4 b = *(const float4*)&W[(size_t)(n0 + row) * CDIM + k0 + q4];
            a.x = to_tf32(a.x); a.y = to_tf32(a.y); a.z = to_tf32(a.z); a.w = to_tf32(a.w);
            b.x = to_tf32(b.x); b.y = to_tf32(b.y); b.z = to_tf32(b.z); b.w = to_tf32(b.w);
            *(float4*)&As[row][q4] = a;
            *(float4*)&Bs[row][q4] = b;
        }
        __syncthreads();

#pragma unroll
        for (int ks = 0; ks < 4; ++ks) {
            const int kk = ks * 8;
            uint32_t af[4][4];
#pragma unroll
            for (int mt = 0; mt < 4; ++mt) {
                const int r0 = wm + mt * 16 + gID;
                af[mt][0] = __float_as_uint(As[r0    ][kk + tig    ]);
                af[mt][1] = __float_as_uint(As[r0 + 8][kk + tig    ]);
                af[mt][2] = __float_as_uint(As[r0    ][kk + tig + 4]);
                af[mt][3] = __float_as_uint(As[r0 + 8][kk + tig + 4]);
            }
            uint32_t bf[4][2];
#pragma unroll
            for (int nt = 0; nt < 4; ++nt) {
                const int rn = wn + nt * 8 + gID;
                bf[nt][0] = __float_as_uint(Bs[rn][kk + tig    ]);
                bf[nt][1] = __float_as_uint(Bs[rn][kk + tig + 4]);
            }
#pragma unroll
            for (int mt = 0; mt < 4; ++mt)
#pragma unroll
                for (int nt = 0; nt < 4; ++nt)
                    mma_tf32(acc[mt][nt], af[mt], bf[nt]);
        }
        __syncthreads();
    }

    // ---- epilogue: +bias, float2 stores (c0,c1 / c2,c3 are adjacent cols)
#pragma unroll
    for (int mt = 0; mt < 4; ++mt) {
#pragma unroll
        for (int nt = 0; nt < 4; ++nt) {
            const int mrow0 = m0 + wm + mt * 16 + gID;
            const int mrow1 = mrow0 + 8;
            const int ncol  = n0 + wn + nt * 8 + 2 * tig;
            const float bx = bias[ncol], by = bias[ncol + 1];
            float2 v0, v1;
            v0.x = acc[mt][nt][0] + bx; v0.y = acc[mt][nt][1] + by;
            v1.x = acc[mt][nt][2] + bx; v1.y = acc[mt][nt][3] + by;
            if (MODE == 0) {
                *(float2*)&out[(size_t)mrow0 * CDIM + ncol] = v0;
                *(float2*)&out[(size_t)mrow1 * CDIM + ncol] = v1;
            } else {
                const int h  = ncol >> 6;
                const int dd = ncol & 63;
                const int b0r = mrow0 >> 11, t0r = mrow0 & (TSEQ - 1);
                const int b1r = mrow1 >> 11, t1r = mrow1 & (TSEQ - 1);
                *(float2*)&out[(((size_t)(b0r * HN + h)) * TSEQ + t0r) * DH + dd] = v0;
                *(float2*)&out[(((size_t)(b1r * HN + h)) * TSEQ + t1r) * DH + dd] = v1;
            }
        }
    }
}

// ----------------------------------------------------------------------------
// Causal flash attention, fp32 with packed f32x2 math, log2-domain softmax.
// Grid: (T/128, B*H). 128 threads/block, 1 query per thread.
// ----------------------------------------------------------------------------
#define BQ  128
#define BKT 64

union F4U { float4 v; ull u[2]; };

__global__ __launch_bounds__(128)
void flash_attn_kernel(const float* __restrict__ Qg,
                       const float* __restrict__ Kg,
                       const float* __restrict__ Vg,
                       float* __restrict__ att)
{
    const int bh = blockIdx.y;
    const int q0 = blockIdx.x * BQ;
    const int tid = threadIdx.x;
    const int q = q0 + tid;

    __shared__ float Ks[BKT][DH];
    __shared__ float Vs[BKT][DH];

    const float qscale = 0.125f * 1.4426950408889634f;   // 1/sqrt(D) * log2(e)

    ull qr2[DH / 2];
    {
        const float* Qp = Qg + ((size_t)bh * TSEQ + q) * DH;
#pragma unroll
        for (int d4 = 0; d4 < DH / 4; ++d4) {
            float4 t = *(const float4*)(Qp + d4 * 4);
            t.x *= qscale; t.y *= qscale; t.z *= qscale; t.w *= qscale;
            F4U u; u.v = t;
            qr2[2 * d4 + 0] = u.u[0];
            qr2[2 * d4 + 1] = u.u[1];
        }
    }

    ull o2[DH / 2];
#pragma unroll
    for (int i = 0; i < DH / 2; ++i) o2[i] = 0ull;
    float m = -CUDART_INF_F;
    float l = 0.f;

    const int ntiles = (q0 + BQ - 1) / BKT + 1;

    for (int kt = 0; kt < ntiles; ++kt) {
        const int kbase = kt * BKT;
        __syncthreads();
        {
            const int r = tid >> 1;
            const int cc = (tid & 1) * 32;
            const float4* kp = (const float4*)(Kg + ((size_t)bh * TSEQ + kbase + r) * DH + cc);
            const float4* vp = (const float4*)(Vg + ((size_t)bh * TSEQ + kbase + r) * DH + cc);
            float4* ks = (float4*)&Ks[r][cc];
            float4* vs = (float4*)&Vs[r][cc];
#pragma unroll
            for (int i = 0; i < 8; ++i) ks[i] = kp[i];
#pragma unroll
            for (int i = 0; i < 8; ++i) vs[i] = vp[i];
        }
        __syncthreads();

        if (kbase > q) continue;   // fully masked tile for this query

#pragma unroll 1
        for (int c = 0; c < BKT; c += 16) {
            float s[16];
            float mt = m;
#pragma unroll
            for (int j = 0; j < 16; ++j) {
                const int kk = c + j;
                ull acc = 0ull;
#pragma unroll
                for (int d4 = 0; d4 < DH / 4; ++d4) {
                    F4U kv; kv.v = *(const float4*)&Ks[kk][d4 * 4];
                    acc = fma2_(qr2[2 * d4 + 0], kv.u[0], acc);
                    acc = fma2_(qr2[2 * d4 + 1], kv.u[1], acc);
                }
                float2 af = unpack2(acc);
                const float sc = af.x + af.y;
                s[j] = (kbase + kk <= q) ? sc : -CUDART_INF_F;
                mt = fmaxf(mt, s[j]);
            }
            const float corr = fast_exp2(m - mt);
            m = mt;
            l *= corr;
            const ull corr2 = pack2(corr);
#pragma unroll
            for (int i = 0; i < DH / 2; ++i) o2[i] = mul2_(o2[i], corr2);
#pragma unroll
            for (int j = 0; j < 16; ++j) {
                const float p = fast_exp2(s[j] - m);
                l += p;
                const ull p2 = pack2(p);
#pragma unroll
                for (int d4 = 0; d4 < DH / 4; ++d4) {
                    F4U vv; vv.v = *(const float4*)&Vs[c + j][d4 * 4];
                    o2[2 * d4 + 0] = fma2_(p2, vv.u[0], o2[2 * d4 + 0]);
                    o2[2 * d4 + 1] = fma2_(p2, vv.u[1], o2[2 * d4 + 1]);
                }
            }
        }
    }

    const float inv = 1.0f / l;
    const int b = bh / HN;
    const int h = bh % HN;
    float* op = att + ((size_t)(b * TSEQ + q)) * CDIM + h * DH;
#pragma unroll
    for (int d4 = 0; d4 < DH / 4; ++d4) {
        float2 lo = unpack2(o2[2 * d4 + 0]);
        float2 hi = unpack2(o2[2 * d4 + 1]);
        float4 v;
        v.x = lo.x * inv; v.y = lo.y * inv;
        v.z = hi.x * inv; v.w = hi.y * inv;
        *(float4*)(op + d4 * 4) = v;
    }
}

// ----------------------------------------------------------------------------
extern "C" void kernel_launch(void* const* d_in, const int* in_sizes, int n_in,
                              void* d_out, int out_size)
{
    const float* x  = (const float*)d_in[0];
    const float* Wq = (const float*)d_in[1];
    const float* bq = (const float*)d_in[2];
    const float* Wk = (const float*)d_in[3];
    const float* bk = (const float*)d_in[4];
    const float* Wv = (const float*)d_in[5];
    const float* bv = (const float*)d_in[6];
    const float* Wo = (const float*)d_in[7];
    const float* bo = (const float*)d_in[8];
    float* out = (float*)d_out;

    float *Qp, *Kp, *Vp, *Ap;
    cudaGetSymbolAddress((void**)&Qp, g_Q);
    cudaGetSymbolAddress((void**)&Kp, g_K);
    cudaGetSymbolAddress((void**)&Vp, g_V);
    cudaGetSymbolAddress((void**)&Ap, g_att);

    dim3 gemm_grid(CDIM / 128, (BSZ * TSEQ) / 128);   // (8, 32)
    gemm_mma_kernel<1><<<gemm_grid, 256>>>(x, Wq, bq, Qp);
    gemm_mma_kernel<1><<<gemm_grid, 256>>>(x, Wk, bk, Kp);
    gemm_mma_kernel<1><<<gemm_grid, 256>>>(x, Wv, bv, Vp);

    dim3 attn_grid(TSEQ / BQ, BSZ * HN);              // (16, 32)
    flash_attn_kernel<<<attn_grid, 128>>>(Qp, Kp, Vp, Ap);

    gemm_mma_kernel<0><<<gemm_grid, 256>>>(Ap, Wo, bo, out);
}

// round 8
// speedup vs baseline: 1.5223x; 1.5223x over previous
#include <cuda_runtime.h>
#include <math_constants.h>
#include <cstdint>

#define BSZ   2
#define TSEQ  2048
#define CDIM  1024
#define HN    16
#define DH    64

// Scratch (allocation-free rule: __device__ globals)
__device__ float g_Q[(size_t)BSZ*HN*TSEQ*DH];   // [B,H,T,D]
__device__ float g_K[(size_t)BSZ*HN*TSEQ*DH];
__device__ float g_V[(size_t)BSZ*HN*TSEQ*DH];
__device__ float g_att[(size_t)BSZ*TSEQ*CDIM];  // [B,T,C]

// ---------------------------------------------------------------------------
// helpers
// ---------------------------------------------------------------------------
__device__ __forceinline__ float fast_exp2(float x) {
    float y;
    asm("ex2.approx.f32 %0, %1;" : "=f"(y) : "f"(x));
    return y;
}

__device__ __forceinline__ float to_tf32(float x) {
    float r;
    asm("cvt.rna.tf32.f32 %0, %1;" : "=f"(r) : "f"(x));
    return r;
}

// tf32 mma.sync (sm_80+ legacy tensor path, compiles at compute_103)
__device__ __forceinline__ void mma_tf32(float* d, const uint32_t* a, const uint32_t* b)
{
    asm volatile(
        "mma.sync.aligned.m16n8k8.row.col.f32.tf32.tf32.f32 "
        "{%0,%1,%2,%3}, {%4,%5,%6,%7}, {%8,%9}, {%0,%1,%2,%3};"
        : "+f"(d[0]), "+f"(d[1]), "+f"(d[2]), "+f"(d[3])
        : "r"(a[0]), "r"(a[1]), "r"(a[2]), "r"(a[3]),
          "r"(b[0]), "r"(b[1]));
}

// ---------------------------------------------------------------------------
// tf32 tensor-core GEMM-NT, double-buffered:
//   out[M,N] = A[M,K] @ W[N,K]^T + bias,  M=4096, N=K=1024
// CTA tile 128x128, 8 warps x (64x32) micro-grid of m16n8k8, K-chunk 32.
// NMAT=3: blockIdx.z selects (W,b,out) among three (fused QKV, shared A).
// MODE 0: out row-major [M,N];  MODE 1: head-split [B,H,T,D]
// ---------------------------------------------------------------------------
#define GPAD 36   // 32 + 4 floats padding: conflict-free fragment gathers
#define GEMM_SMEM (4 * 128 * GPAD * 4)   // 2 buffers x (As + Bs) = 73728 B

template <int MODE, int NMAT>
__global__ __launch_bounds__(256)
void gemm_mma_kernel(const float* __restrict__ A,
                     const float* __restrict__ W0, const float* __restrict__ W1,
                     const float* __restrict__ W2,
                     const float* __restrict__ b0, const float* __restrict__ b1,
                     const float* __restrict__ b2,
                     float* __restrict__ o0, float* __restrict__ o1,
                     float* __restrict__ o2)
{
    extern __shared__ float smem[];
    float (*As)[128][GPAD] = (float (*)[128][GPAD])(smem);
    float (*Bs)[128][GPAD] = (float (*)[128][GPAD])(smem + 2 * 128 * GPAD);

    const int z = (NMAT == 3) ? (int)blockIdx.z : 0;
    const float* __restrict__ W    = (z == 0) ? W0 : (z == 1 ? W1 : W2);
    const float* __restrict__ bias = (z == 0) ? b0 : (z == 1 ? b1 : b2);
    float* __restrict__ out        = (z == 0) ? o0 : (z == 1 ? o1 : o2);

    const int tid  = threadIdx.x;
    const int wid  = tid >> 5;
    const int lane = tid & 31;
    const int gID  = lane >> 2;      // 0..7
    const int tig  = lane & 3;       // 0..3
    const int n0 = blockIdx.x * 128;
    const int m0 = blockIdx.y * 128;
    const int wm = (wid >> 2) * 64;  // warp m-offset within tile
    const int wn = (wid & 3) * 32;   // warp n-offset within tile

    // per-thread staging: 4 float4 slots each of A and W per chunk
    const int srow = tid >> 1;               // rows covered: tid/2 and tid/2+... see below
    // We reuse the simpler idx mapping: slot idx = tid + i*256, row = idx>>3, q4 = (idx&7)*4
    float4 ra[4], rb[4];

    float acc[4][4][4];              // [mt][nt][reg]
#pragma unroll
    for (int mt = 0; mt < 4; ++mt)
#pragma unroll
        for (int nt = 0; nt < 4; ++nt)
#pragma unroll
            for (int r = 0; r < 4; ++r) acc[mt][nt][r] = 0.f;

    // ---- prologue: load + store chunk 0
#pragma unroll
    for (int i = 0; i < 4; ++i) {
        const int idx = tid + i * 256;
        const int row = idx >> 3;
        const int q4  = (idx & 7) * 4;
        ra[i] = *(const float4*)&A[(size_t)(m0 + row) * CDIM + q4];
        rb[i] = *(const float4*)&W[(size_t)(n0 + row) * CDIM + q4];
    }
#pragma unroll
    for (int i = 0; i < 4; ++i) {
        const int idx = tid + i * 256;
        const int row = idx >> 3;
        const int q4  = (idx & 7) * 4;
        float4 a = ra[i], b = rb[i];
        a.x = to_tf32(a.x); a.y = to_tf32(a.y); a.z = to_tf32(a.z); a.w = to_tf32(a.w);
        b.x = to_tf32(b.x); b.y = to_tf32(b.y); b.z = to_tf32(b.z); b.w = to_tf32(b.w);
        *(float4*)&As[0][row][q4] = a;
        *(float4*)&Bs[0][row][q4] = b;
    }
    __syncthreads();

    for (int c = 0; c < 32; ++c) {
        const int cur = c & 1;
        // ---- issue global loads for chunk c+1 (latency hidden by MMAs below)
        if (c + 1 < 32) {
            const int k0 = (c + 1) * 32;
#pragma unroll
            for (int i = 0; i < 4; ++i) {
                const int idx = tid + i * 256;
                const int row = idx >> 3;
                const int q4  = (idx & 7) * 4;
                ra[i] = *(const float4*)&A[(size_t)(m0 + row) * CDIM + k0 + q4];
                rb[i] = *(const float4*)&W[(size_t)(n0 + row) * CDIM + k0 + q4];
            }
        }

        // ---- MMAs on chunk c
#pragma unroll
        for (int ks = 0; ks < 4; ++ks) {
            const int kk = ks * 8;
            uint32_t af[4][4];
#pragma unroll
            for (int mt = 0; mt < 4; ++mt) {
                const int r0 = wm + mt * 16 + gID;
                af[mt][0] = __float_as_uint(As[cur][r0    ][kk + tig    ]);
                af[mt][1] = __float_as_uint(As[cur][r0 + 8][kk + tig    ]);
                af[mt][2] = __float_as_uint(As[cur][r0    ][kk + tig + 4]);
                af[mt][3] = __float_as_uint(As[cur][r0 + 8][kk + tig + 4]);
            }
            uint32_t bf[4][2];
#pragma unroll
            for (int nt = 0; nt < 4; ++nt) {
                const int rn = wn + nt * 8 + gID;
                bf[nt][0] = __float_as_uint(Bs[cur][rn][kk + tig    ]);
                bf[nt][1] = __float_as_uint(Bs[cur][rn][kk + tig + 4]);
            }
#pragma unroll
            for (int mt = 0; mt < 4; ++mt)
#pragma unroll
                for (int nt = 0; nt < 4; ++nt)
                    mma_tf32(acc[mt][nt], af[mt], bf[nt]);
        }
        __syncthreads();     // all warps done reading buf[cur^1]'s predecessor reads

        if (c + 1 < 32) {
            const int nxt = cur ^ 1;
#pragma unroll
            for (int i = 0; i < 4; ++i) {
                const int idx = tid + i * 256;
                const int row = idx >> 3;
                const int q4  = (idx & 7) * 4;
                float4 a = ra[i], b = rb[i];
                a.x = to_tf32(a.x); a.y = to_tf32(a.y); a.z = to_tf32(a.z); a.w = to_tf32(a.w);
                b.x = to_tf32(b.x); b.y = to_tf32(b.y); b.z = to_tf32(b.z); b.w = to_tf32(b.w);
                *(float4*)&As[nxt][row][q4] = a;
                *(float4*)&Bs[nxt][row][q4] = b;
            }
            __syncthreads(); // chunk c+1 visible before next iteration computes
        }
    }

    // ---- epilogue: +bias, float2 stores (c0,c1 / c2,c3 are adjacent cols)
#pragma unroll
    for (int mt = 0; mt < 4; ++mt) {
#pragma unroll
        for (int nt = 0; nt < 4; ++nt) {
            const int mrow0 = m0 + wm + mt * 16 + gID;
            const int mrow1 = mrow0 + 8;
            const int ncol  = n0 + wn + nt * 8 + 2 * tig;
            const float bx = bias[ncol], by = bias[ncol + 1];
            float2 v0, v1;
            v0.x = acc[mt][nt][0] + bx; v0.y = acc[mt][nt][1] + by;
            v1.x = acc[mt][nt][2] + bx; v1.y = acc[mt][nt][3] + by;
            if (MODE == 0) {
                *(float2*)&out[(size_t)mrow0 * CDIM + ncol] = v0;
                *(float2*)&out[(size_t)mrow1 * CDIM + ncol] = v1;
            } else {
                const int h  = ncol >> 6;
                const int dd = ncol & 63;
                const int b0r = mrow0 >> 11, t0r = mrow0 & (TSEQ - 1);
                const int b1r = mrow1 >> 11, t1r = mrow1 & (TSEQ - 1);
                *(float2*)&out[(((size_t)(b0r * HN + h)) * TSEQ + t0r) * DH + dd] = v0;
                *(float2*)&out[(((size_t)(b1r * HN + h)) * TSEQ + t1r) * DH + dd] = v1;
            }
        }
    }
}

// ----------------------------------------------------------------------------
// Causal flash attention, fp32 scalar (R2-proven body), log2-domain softmax.
// Grid: (T/128, B*H). 128 threads/block, 1 query per thread.
// Added: warp-uniform skip of fully-masked tiles + per-thread break past the
// diagonal chunk (no barriers inside the chunk loop -> divergence-safe).
// ----------------------------------------------------------------------------
#define BQ  128
#define BKT 64

__global__ __launch_bounds__(128)
void flash_attn_kernel(const float* __restrict__ Qg,
                       const float* __restrict__ Kg,
                       const float* __restrict__ Vg,
                       float* __restrict__ att)
{
    const int bh = blockIdx.y;              // 0..B*H-1
    const int q0 = blockIdx.x * BQ;
    const int tid = threadIdx.x;
    const int q = q0 + tid;

    __shared__ float Ks[BKT][DH];
    __shared__ float Vs[BKT][DH];

    // scale = 1/sqrt(D) folded with log2(e) so scores live in log2 domain
    const float qscale = 0.125f * 1.4426950408889634f;

    float qr[DH];
    {
        const float* Qp = Qg + ((size_t)bh * TSEQ + q) * DH;
#pragma unroll
        for (int d4 = 0; d4 < DH / 4; d4++) {
            float4 t = *(const float4*)(Qp + d4 * 4);
            qr[d4 * 4 + 0] = t.x * qscale;
            qr[d4 * 4 + 1] = t.y * qscale;
            qr[d4 * 4 + 2] = t.z * qscale;
            qr[d4 * 4 + 3] = t.w * qscale;
        }
    }

    float o[DH];
#pragma unroll
    for (int d = 0; d < DH; d++) o[d] = 0.f;
    float m = -CUDART_INF_F;
    float l = 0.f;

    const int ntiles = (q0 + BQ - 1) / BKT + 1;   // covers keys <= q0+BQ-1

    for (int kt = 0; kt < ntiles; kt++) {
        const int kbase = kt * BKT;
        __syncthreads();   // previous tile fully consumed
        {
            const int r = tid >> 1;
            const int c = (tid & 1) * 32;
            const float4* kp = (const float4*)(Kg + ((size_t)bh * TSEQ + kbase + r) * DH + c);
            const float4* vp = (const float4*)(Vg + ((size_t)bh * TSEQ + kbase + r) * DH + c);
            float4* ks = (float4*)&Ks[r][c];
            float4* vs = (float4*)&Vs[r][c];
#pragma unroll
            for (int i = 0; i < 8; i++) ks[i] = kp[i];
#pragma unroll
            for (int i = 0; i < 8; i++) vs[i] = vp[i];
        }
        __syncthreads();

        if (kbase > q) continue;   // fully masked tile for this query

#pragma unroll 1
        for (int c = 0; c < BKT; c += 16) {
            if (kbase + c > q) break;   // remaining chunks fully masked
            float s[16];
            float mt = m;
#pragma unroll
            for (int j = 0; j < 16; j++) {
                const int kk = c + j;
                float acc = 0.f;
#pragma unroll
                for (int d4 = 0; d4 < DH / 4; d4++) {
                    float4 kv = *(const float4*)&Ks[kk][d4 * 4];
                    acc += qr[d4 * 4 + 0] * kv.x;
                    acc += qr[d4 * 4 + 1] * kv.y;
                    acc += qr[d4 * 4 + 2] * kv.z;
                    acc += qr[d4 * 4 + 3] * kv.w;
                }
                s[j] = (kbase + kk <= q) ? acc : -CUDART_INF_F;
                mt = fmaxf(mt, s[j]);
            }
            const float corr = fast_exp2(m - mt);
            m = mt;
            l *= corr;
#pragma unroll
            for (int d = 0; d < DH; d++) o[d] *= corr;
#pragma unroll
            for (int j = 0; j < 16; j++) {
                const float p = fast_exp2(s[j] - m);
                l += p;
#pragma unroll
                for (int d4 = 0; d4 < DH / 4; d4++) {
                    float4 vv = *(const float4*)&Vs[c + j][d4 * 4];
                    o[d4 * 4 + 0] += p * vv.x;
                    o[d4 * 4 + 1] += p * vv.y;
                    o[d4 * 4 + 2] += p * vv.z;
                    o[d4 * 4 + 3] += p * vv.w;
                }
            }
        }
    }

    const float inv = 1.0f / l;
    const int b = bh / HN;
    const int h = bh % HN;
    float* op = att + ((size_t)(b * TSEQ + q)) * CDIM + h * DH;
#pragma unroll
    for (int d4 = 0; d4 < DH / 4; d4++) {
        float4 v;
        v.x = o[d4 * 4 + 0] * inv;
        v.y = o[d4 * 4 + 1] * inv;
        v.z = o[d4 * 4 + 2] * inv;
        v.w = o[d4 * 4 + 3] * inv;
        *(float4*)(op + d4 * 4) = v;
    }
}

// ----------------------------------------------------------------------------
extern "C" void kernel_launch(void* const* d_in, const int* in_sizes, int n_in,
                              void* d_out, int out_size)
{
    const float* x  = (const float*)d_in[0];
    const float* Wq = (const float*)d_in[1];
    const float* bq = (const float*)d_in[2];
    const float* Wk = (const float*)d_in[3];
    const float* bk = (const float*)d_in[4];
    const float* Wv = (const float*)d_in[5];
    const float* bv = (const float*)d_in[6];
    const float* Wo = (const float*)d_in[7];
    const float* bo = (const float*)d_in[8];
    float* out = (float*)d_out;

    float *Qp, *Kp, *Vp, *Ap;
    cudaGetSymbolAddress((void**)&Qp, g_Q);
    cudaGetSymbolAddress((void**)&Kp, g_K);
    cudaGetSymbolAddress((void**)&Vp, g_V);
    cudaGetSymbolAddress((void**)&Ap, g_att);

    cudaFuncSetAttribute(gemm_mma_kernel<1, 3>,
                         cudaFuncAttributeMaxDynamicSharedMemorySize, GEMM_SMEM);
    cudaFuncSetAttribute(gemm_mma_kernel<0, 1>,
                         cudaFuncAttributeMaxDynamicSharedMemorySize, GEMM_SMEM);

    // fused Q/K/V projections: z selects the weight/bias/output triple
    dim3 qkv_grid(CDIM / 128, (BSZ * TSEQ) / 128, 3);   // (8, 32, 3)
    gemm_mma_kernel<1, 3><<<qkv_grid, 256, GEMM_SMEM>>>(
        x, Wq, Wk, Wv, bq, bk, bv, Qp, Kp, Vp);

    dim3 attn_grid(TSEQ / BQ, BSZ * HN);                // (16, 32)
    flash_attn_kernel<<<attn_grid, 128>>>(Qp, Kp, Vp, Ap);

    dim3 o_grid(CDIM / 128, (BSZ * TSEQ) / 128, 1);     // (8, 32)
    gemm_mma_kernel<0, 1><<<o_grid, 256, GEMM_SMEM>>>(
        Ap, Wo, Wo, Wo, bo, bo, bo, out, out, out);
}

// round 9
// speedup vs baseline: 3.3877x; 2.2254x over previous
#include <cuda_runtime.h>
#include <math_constants.h>
#include <cstdint>

#define BSZ   2
#define TSEQ  2048
#define CDIM  1024
#define HN    16
#define DH    64

// Scratch (allocation-free rule: __device__ globals)
__device__ float g_Q[(size_t)BSZ*HN*TSEQ*DH];   // [B,H,T,D]
__device__ float g_K[(size_t)BSZ*HN*TSEQ*DH];
__device__ float g_V[(size_t)BSZ*HN*TSEQ*DH];
__device__ float g_att[(size_t)BSZ*TSEQ*CDIM];  // [B,T,C]

// ---------------------------------------------------------------------------
// helpers
// ---------------------------------------------------------------------------
__device__ __forceinline__ float fast_exp2(float x) {
    float y;
    asm("ex2.approx.f32 %0, %1;" : "=f"(y) : "f"(x));
    return y;
}

__device__ __forceinline__ float to_tf32(float x) {
    float r;
    asm("cvt.rna.tf32.f32 %0, %1;" : "=f"(r) : "f"(x));
    return r;
}

// pack two f32 into bf16x2: low half <- lo, high half <- hi
__device__ __forceinline__ uint32_t pack_bf16x2(float lo, float hi) {
    uint32_t r;
    asm("cvt.rn.bf16x2.f32 %0, %1, %2;" : "=r"(r) : "f"(hi), "f"(lo));
    return r;
}
__device__ __forceinline__ float bf16lo_f(uint32_t w) { return __uint_as_float(w << 16); }
__device__ __forceinline__ float bf16hi_f(uint32_t w) { return __uint_as_float(w & 0xFFFF0000u); }

// tf32 mma.sync m16n8k8 (legacy tensor path, compiles at compute_103)
__device__ __forceinline__ void mma_tf32(float* d, const uint32_t* a, const uint32_t* b)
{
    asm volatile(
        "mma.sync.aligned.m16n8k8.row.col.f32.tf32.tf32.f32 "
        "{%0,%1,%2,%3}, {%4,%5,%6,%7}, {%8,%9}, {%0,%1,%2,%3};"
        : "+f"(d[0]), "+f"(d[1]), "+f"(d[2]), "+f"(d[3])
        : "r"(a[0]), "r"(a[1]), "r"(a[2]), "r"(a[3]),
          "r"(b[0]), "r"(b[1]));
}

// bf16 mma.sync m16n8k16
__device__ __forceinline__ void mma_bf16(float* d, const uint32_t* a, uint32_t b0, uint32_t b1)
{
    asm volatile(
        "mma.sync.aligned.m16n8k16.row.col.f32.bf16.bf16.f32 "
        "{%0,%1,%2,%3}, {%4,%5,%6,%7}, {%8,%9}, {%0,%1,%2,%3};"
        : "+f"(d[0]), "+f"(d[1]), "+f"(d[2]), "+f"(d[3])
        : "r"(a[0]), "r"(a[1]), "r"(a[2]), "r"(a[3]),
          "r"(b0), "r"(b1));
}

// ---------------------------------------------------------------------------
// tf32 tensor-core GEMM-NT, double-buffered (proven R7 kernel):
//   out[M,N] = A[M,K] @ W[N,K]^T + bias,  M=4096, N=K=1024
// ---------------------------------------------------------------------------
#define GPAD 36
#define GEMM_SMEM (4 * 128 * GPAD * 4)   // 2 buffers x (As + Bs) = 73728 B

template <int MODE, int NMAT>
__global__ __launch_bounds__(256)
void gemm_mma_kernel(const float* __restrict__ A,
                     const float* __restrict__ W0, const float* __restrict__ W1,
                     const float* __restrict__ W2,
                     const float* __restrict__ b0, const float* __restrict__ b1,
                     const float* __restrict__ b2,
                     float* __restrict__ o0, float* __restrict__ o1,
                     float* __restrict__ o2)
{
    extern __shared__ float smem[];
    float (*As)[128][GPAD] = (float (*)[128][GPAD])(smem);
    float (*Bs)[128][GPAD] = (float (*)[128][GPAD])(smem + 2 * 128 * GPAD);

    const int z = (NMAT == 3) ? (int)blockIdx.z : 0;
    const float* __restrict__ W    = (z == 0) ? W0 : (z == 1 ? W1 : W2);
    const float* __restrict__ bias = (z == 0) ? b0 : (z == 1 ? b1 : b2);
    float* __restrict__ out        = (z == 0) ? o0 : (z == 1 ? o1 : o2);

    const int tid  = threadIdx.x;
    const int wid  = tid >> 5;
    const int lane = tid & 31;
    const int gID  = lane >> 2;
    const int tig  = lane & 3;
    const int n0 = blockIdx.x * 128;
    const int m0 = blockIdx.y * 128;
    const int wm = (wid >> 2) * 64;
    const int wn = (wid & 3) * 32;

    float4 ra[4], rb[4];

    float acc[4][4][4];
#pragma unroll
    for (int mt = 0; mt < 4; ++mt)
#pragma unroll
        for (int nt = 0; nt < 4; ++nt)
#pragma unroll
            for (int r = 0; r < 4; ++r) acc[mt][nt][r] = 0.f;

#pragma unroll
    for (int i = 0; i < 4; ++i) {
        const int idx = tid + i * 256;
        const int row = idx >> 3;
        const int q4  = (idx & 7) * 4;
        ra[i] = *(const float4*)&A[(size_t)(m0 + row) * CDIM + q4];
        rb[i] = *(const float4*)&W[(size_t)(n0 + row) * CDIM + q4];
    }
#pragma unroll
    for (int i = 0; i < 4; ++i) {
        const int idx = tid + i * 256;
        const int row = idx >> 3;
        const int q4  = (idx & 7) * 4;
        float4 a = ra[i], b = rb[i];
        a.x = to_tf32(a.x); a.y = to_tf32(a.y); a.z = to_tf32(a.z); a.w = to_tf32(a.w);
        b.x = to_tf32(b.x); b.y = to_tf32(b.y); b.z = to_tf32(b.z); b.w = to_tf32(b.w);
        *(float4*)&As[0][row][q4] = a;
        *(float4*)&Bs[0][row][q4] = b;
    }
    __syncthreads();

    for (int c = 0; c < 32; ++c) {
        const int cur = c & 1;
        if (c + 1 < 32) {
            const int k0 = (c + 1) * 32;
#pragma unroll
            for (int i = 0; i < 4; ++i) {
                const int idx = tid + i * 256;
                const int row = idx >> 3;
                const int q4  = (idx & 7) * 4;
                ra[i] = *(const float4*)&A[(size_t)(m0 + row) * CDIM + k0 + q4];
                rb[i] = *(const float4*)&W[(size_t)(n0 + row) * CDIM + k0 + q4];
            }
        }

#pragma unroll
        for (int ks = 0; ks < 4; ++ks) {
            const int kk = ks * 8;
            uint32_t af[4][4];
#pragma unroll
            for (int mt = 0; mt < 4; ++mt) {
                const int r0 = wm + mt * 16 + gID;
                af[mt][0] = __float_as_uint(As[cur][r0    ][kk + tig    ]);
                af[mt][1] = __float_as_uint(As[cur][r0 + 8][kk + tig    ]);
                af[mt][2] = __float_as_uint(As[cur][r0    ][kk + tig + 4]);
                af[mt][3] = __float_as_uint(As[cur][r0 + 8][kk + tig + 4]);
            }
            uint32_t bf[4][2];
#pragma unroll
            for (int nt = 0; nt < 4; ++nt) {
                const int rn = wn + nt * 8 + gID;
                bf[nt][0] = __float_as_uint(Bs[cur][rn][kk + tig    ]);
                bf[nt][1] = __float_as_uint(Bs[cur][rn][kk + tig + 4]);
            }
#pragma unroll
            for (int mt = 0; mt < 4; ++mt)
#pragma unroll
                for (int nt = 0; nt < 4; ++nt)
                    mma_tf32(acc[mt][nt], af[mt], bf[nt]);
        }
        __syncthreads();

        if (c + 1 < 32) {
            const int nxt = cur ^ 1;
#pragma unroll
            for (int i = 0; i < 4; ++i) {
                const int idx = tid + i * 256;
                const int row = idx >> 3;
                const int q4  = (idx & 7) * 4;
                float4 a = ra[i], b = rb[i];
                a.x = to_tf32(a.x); a.y = to_tf32(a.y); a.z = to_tf32(a.z); a.w = to_tf32(a.w);
                b.x = to_tf32(b.x); b.y = to_tf32(b.y); b.z = to_tf32(b.z); b.w = to_tf32(b.w);
                *(float4*)&As[nxt][row][q4] = a;
                *(float4*)&Bs[nxt][row][q4] = b;
            }
            __syncthreads();
        }
    }

#pragma unroll
    for (int mt = 0; mt < 4; ++mt) {
#pragma unroll
        for (int nt = 0; nt < 4; ++nt) {
            const int mrow0 = m0 + wm + mt * 16 + gID;
            const int mrow1 = mrow0 + 8;
            const int ncol  = n0 + wn + nt * 8 + 2 * tig;
            const float bx = bias[ncol], by = bias[ncol + 1];
            float2 v0, v1;
            v0.x = acc[mt][nt][0] + bx; v0.y = acc[mt][nt][1] + by;
            v1.x = acc[mt][nt][2] + bx; v1.y = acc[mt][nt][3] + by;
            if (MODE == 0) {
                *(float2*)&out[(size_t)mrow0 * CDIM + ncol] = v0;
                *(float2*)&out[(size_t)mrow1 * CDIM + ncol] = v1;
            } else {
                const int h  = ncol >> 6;
                const int dd = ncol & 63;
                const int b0r = mrow0 >> 11, t0r = mrow0 & (TSEQ - 1);
                const int b1r = mrow1 >> 11, t1r = mrow1 & (TSEQ - 1);
                *(float2*)&out[(((size_t)(b0r * HN + h)) * TSEQ + t0r) * DH + dd] = v0;
                *(float2*)&out[(((size_t)(b1r * HN + h)) * TSEQ + t1r) * DH + dd] = v1;
            }
        }
    }
}

// ----------------------------------------------------------------------------
// Tensor-core causal flash attention (bf16 split-3, ~fp32 accurate).
// Block: 128 threads (4 warps). Q-tile 64 (16 rows per warp), KV-tile 64.
// Grid: (T/64, B*H).
// S = Q K^T via mma.bf16 (Qh*Kh + Qh*Kl + Ql*Kh); online softmax in registers;
// P fragments feed PV MMA directly (C-layout == A-layout identity).
// ----------------------------------------------------------------------------
#define KPAD 36   // words per smem row: 32 data + 4 pad (bank = 4*gID+tig, distinct)

__global__ __launch_bounds__(128)
void flash_attn_mma_kernel(const float* __restrict__ Qg,
                           const float* __restrict__ Kg,
                           const float* __restrict__ Vg,
                           float* __restrict__ att)
{
    __shared__ uint32_t sKhi[64 * KPAD];   // [key][d/2]  bf16x2 (d-pairs)
    __shared__ uint32_t sKlo[64 * KPAD];
    __shared__ uint32_t sVhi[64 * KPAD];   // [d][key/2]  bf16x2 (key-pairs)
    __shared__ uint32_t sVlo[64 * KPAD];

    const int bh  = blockIdx.y;
    const int bx  = blockIdx.x;
    const int q0  = bx * 64;
    const int tid = threadIdx.x;
    const int wid = tid >> 5;
    const int lane = tid & 31;
    const int gID = lane >> 2;
    const int tig = lane & 3;

    const int rA = q0 + wid * 16 + gID;   // first row this thread touches
    const int rB = rA + 8;

    const float qscale = 0.125f * 1.4426950408889634f;   // 1/sqrt(D) * log2(e)

    // ---- Q fragments in registers (A-layout m16k16), hi/lo split
    uint32_t qhi[4][4], qlo[4][4];
    {
        const float* QA = Qg + ((size_t)bh * TSEQ + rA) * DH;
        const float* QB = Qg + ((size_t)bh * TSEQ + rB) * DH;
#pragma unroll
        for (int ks = 0; ks < 4; ++ks) {
            const int d0 = 16 * ks + 2 * tig;
            const int d1 = d0 + 8;
            float2 fa0 = *(const float2*)(QA + d0);
            float2 fb0 = *(const float2*)(QB + d0);
            float2 fa1 = *(const float2*)(QA + d1);
            float2 fb1 = *(const float2*)(QB + d1);
            fa0.x *= qscale; fa0.y *= qscale; fb0.x *= qscale; fb0.y *= qscale;
            fa1.x *= qscale; fa1.y *= qscale; fb1.x *= qscale; fb1.y *= qscale;
            uint32_t h;
            h = pack_bf16x2(fa0.x, fa0.y); qhi[ks][0] = h;
            qlo[ks][0] = pack_bf16x2(fa0.x - bf16lo_f(h), fa0.y - bf16hi_f(h));
            h = pack_bf16x2(fb0.x, fb0.y); qhi[ks][1] = h;
            qlo[ks][1] = pack_bf16x2(fb0.x - bf16lo_f(h), fb0.y - bf16hi_f(h));
            h = pack_bf16x2(fa1.x, fa1.y); qhi[ks][2] = h;
            qlo[ks][2] = pack_bf16x2(fa1.x - bf16lo_f(h), fa1.y - bf16hi_f(h));
            h = pack_bf16x2(fb1.x, fb1.y); qhi[ks][3] = h;
            qlo[ks][3] = pack_bf16x2(fb1.x - bf16lo_f(h), fb1.y - bf16hi_f(h));
        }
    }

    float O[8][4];
#pragma unroll
    for (int nt = 0; nt < 8; ++nt)
#pragma unroll
        for (int r = 0; r < 4; ++r) O[nt][r] = 0.f;
    float mA = -1e30f, mB = -1e30f, lA = 0.f, lB = 0.f;

    const int ntiles = bx + 1;

    for (int kt = 0; kt < ntiles; ++kt) {
        const int kbase = kt * 64;
        __syncthreads();   // previous tile fully consumed

        // ---- stage K: [key][d-pair] bf16x2 hi/lo
        {
            const int key = tid & 63;
            const int dh  = tid >> 6;             // 0..1 -> d base 32*dh
            const float* kp = Kg + ((size_t)bh * TSEQ + kbase + key) * DH + dh * 32;
            uint32_t* ph = &sKhi[key * KPAD + dh * 16];
            uint32_t* pl = &sKlo[key * KPAD + dh * 16];
#pragma unroll
            for (int i = 0; i < 8; ++i) {
                float4 v = ((const float4*)kp)[i];
                uint32_t h0 = pack_bf16x2(v.x, v.y);
                uint32_t h1 = pack_bf16x2(v.z, v.w);
                ph[2 * i]     = h0;
                ph[2 * i + 1] = h1;
                pl[2 * i]     = pack_bf16x2(v.x - bf16lo_f(h0), v.y - bf16hi_f(h0));
                pl[2 * i + 1] = pack_bf16x2(v.z - bf16lo_f(h1), v.w - bf16hi_f(h1));
            }
        }
        // ---- stage V transposed: [d][key-pair] bf16x2 hi/lo
        {
            const int p  = tid & 31;              // key pair index
            const int dg = tid >> 5;              // 0..3 -> d base 16*dg
            const float* v0 = Vg + ((size_t)bh * TSEQ + kbase + 2 * p) * DH + dg * 16;
            const float* v1 = v0 + DH;
#pragma unroll
            for (int i = 0; i < 4; ++i) {
                float4 a = ((const float4*)v0)[i];
                float4 b = ((const float4*)v1)[i];
                const int d0 = dg * 16 + 4 * i;
                float ae[4] = {a.x, a.y, a.z, a.w};
                float be[4] = {b.x, b.y, b.z, b.w};
#pragma unroll
                for (int e = 0; e < 4; ++e) {
                    uint32_t h = pack_bf16x2(ae[e], be[e]);
                    sVhi[(d0 + e) * KPAD + p] = h;
                    sVlo[(d0 + e) * KPAD + p] =
                        pack_bf16x2(ae[e] - bf16lo_f(h), be[e] - bf16hi_f(h));
                }
            }
        }
        __syncthreads();

        // ---- QK^T: S[16 x 64] per warp, 8 n-tiles
        float S[8][4];
#pragma unroll
        for (int nt = 0; nt < 8; ++nt) {
            float c[4] = {0.f, 0.f, 0.f, 0.f};
            const uint32_t* rh = &sKhi[(8 * nt + gID) * KPAD];
            const uint32_t* rl = &sKlo[(8 * nt + gID) * KPAD];
#pragma unroll
            for (int ks = 0; ks < 4; ++ks) {
                const uint32_t b0h = rh[8 * ks + tig];
                const uint32_t b1h = rh[8 * ks + 4 + tig];
                const uint32_t b0l = rl[8 * ks + tig];
                const uint32_t b1l = rl[8 * ks + 4 + tig];
                mma_bf16(c, qhi[ks], b0h, b1h);
                mma_bf16(c, qhi[ks], b0l, b1l);
                mma_bf16(c, qlo[ks], b0h, b1h);
            }
            S[nt][0] = c[0]; S[nt][1] = c[1]; S[nt][2] = c[2]; S[nt][3] = c[3];
        }

        // ---- causal mask on the diagonal tile (kbase == q0)
        if (kt == bx) {
#pragma unroll
            for (int nt = 0; nt < 8; ++nt) {
                const int col = kbase + 8 * nt + 2 * tig;
                if (col     > rA) S[nt][0] = -1e30f;
                if (col + 1 > rA) S[nt][1] = -1e30f;
                if (col     > rB) S[nt][2] = -1e30f;
                if (col + 1 > rB) S[nt][3] = -1e30f;
            }
        }

        // ---- online softmax (log2 domain; scores already scaled)
        float tmA = -1e30f, tmB = -1e30f;
#pragma unroll
        for (int nt = 0; nt < 8; ++nt) {
            tmA = fmaxf(tmA, fmaxf(S[nt][0], S[nt][1]));
            tmB = fmaxf(tmB, fmaxf(S[nt][2], S[nt][3]));
        }
        tmA = fmaxf(tmA, __shfl_xor_sync(0xffffffffu, tmA, 1));
        tmA = fmaxf(tmA, __shfl_xor_sync(0xffffffffu, tmA, 2));
        tmB = fmaxf(tmB, __shfl_xor_sync(0xffffffffu, tmB, 1));
        tmB = fmaxf(tmB, __shfl_xor_sync(0xffffffffu, tmB, 2));

        const float nmA = fmaxf(mA, tmA);
        const float nmB = fmaxf(mB, tmB);
        const float corrA = fast_exp2(mA - nmA);
        const float corrB = fast_exp2(mB - nmB);
        mA = nmA; mB = nmB;
        lA *= corrA; lB *= corrB;
#pragma unroll
        for (int nt = 0; nt < 8; ++nt) {
            O[nt][0] *= corrA; O[nt][1] *= corrA;
            O[nt][2] *= corrB; O[nt][3] *= corrB;
        }

        // p = exp2(s - m), row sums, and bf16 hi/lo packs (P->A fragment identity)
        uint32_t ph[8][2], pl[8][2];
        float sA = 0.f, sB = 0.f;
#pragma unroll
        for (int nt = 0; nt < 8; ++nt) {
            const float p0 = fast_exp2(S[nt][0] - nmA);
            const float p1 = fast_exp2(S[nt][1] - nmA);
            const float p2 = fast_exp2(S[nt][2] - nmB);
            const float p3 = fast_exp2(S[nt][3] - nmB);
            sA += p0 + p1; sB += p2 + p3;
            uint32_t h;
            h = pack_bf16x2(p0, p1); ph[nt][0] = h;
            pl[nt][0] = pack_bf16x2(p0 - bf16lo_f(h), p1 - bf16hi_f(h));
            h = pack_bf16x2(p2, p3); ph[nt][1] = h;
            pl[nt][1] = pack_bf16x2(p2 - bf16lo_f(h), p3 - bf16hi_f(h));
        }
        sA += __shfl_xor_sync(0xffffffffu, sA, 1);
        sA += __shfl_xor_sync(0xffffffffu, sA, 2);
        sB += __shfl_xor_sync(0xffffffffu, sB, 1);
        sB += __shfl_xor_sync(0xffffffffu, sB, 2);
        lA += sA; lB += sB;

        // ---- PV: O[16 x 64] += P[16 x 64] @ V[64 x 64]
#pragma unroll
        for (int dnt = 0; dnt < 8; ++dnt) {
            const uint32_t* rh = &sVhi[(8 * dnt + gID) * KPAD];
            const uint32_t* rl = &sVlo[(8 * dnt + gID) * KPAD];
#pragma unroll
            for (int ks = 0; ks < 4; ++ks) {
                uint32_t ah[4] = {ph[2 * ks][0], ph[2 * ks][1],
                                  ph[2 * ks + 1][0], ph[2 * ks + 1][1]};
                uint32_t al[4] = {pl[2 * ks][0], pl[2 * ks][1],
                                  pl[2 * ks + 1][0], pl[2 * ks + 1][1]};
                const uint32_t b0h = rh[8 * ks + tig];
                const uint32_t b1h = rh[8 * ks + 4 + tig];
                const uint32_t b0l = rl[8 * ks + tig];
                const uint32_t b1l = rl[8 * ks + 4 + tig];
                mma_bf16(O[dnt], ah, b0h, b1h);
                mma_bf16(O[dnt], ah, b0l, b1l);
                mma_bf16(O[dnt], al, b0h, b1h);
            }
        }
    }

    // ---- epilogue: normalize and store to [B,T,C]
    const float invA = 1.0f / lA;
    const float invB = 1.0f / lB;
    const int b = bh >> 4;
    const int h = bh & 15;
    float* oA = att + ((size_t)(b * TSEQ + rA)) * CDIM + h * DH;
    float* oB = att + ((size_t)(b * TSEQ + rB)) * CDIM + h * DH;
#pragma unroll
    for (int nt = 0; nt < 8; ++nt) {
        const int col = 8 * nt + 2 * tig;
        float2 vA, vB;
        vA.x = O[nt][0] * invA; vA.y = O[nt][1] * invA;
        vB.x = O[nt][2] * invB; vB.y = O[nt][3] * invB;
        *(float2*)(oA + col) = vA;
        *(float2*)(oB + col) = vB;
    }
}

// ----------------------------------------------------------------------------
extern "C" void kernel_launch(void* const* d_in, const int* in_sizes, int n_in,
                              void* d_out, int out_size)
{
    const float* x  = (const float*)d_in[0];
    const float* Wq = (const float*)d_in[1];
    const float* bq = (const float*)d_in[2];
    const float* Wk = (const float*)d_in[3];
    const float* bk = (const float*)d_in[4];
    const float* Wv = (const float*)d_in[5];
    const float* bv = (const float*)d_in[6];
    const float* Wo = (const float*)d_in[7];
    const float* bo = (const float*)d_in[8];
    float* out = (float*)d_out;

    float *Qp, *Kp, *Vp, *Ap;
    cudaGetSymbolAddress((void**)&Qp, g_Q);
    cudaGetSymbolAddress((void**)&Kp, g_K);
    cudaGetSymbolAddress((void**)&Vp, g_V);
    cudaGetSymbolAddress((void**)&Ap, g_att);

    cudaFuncSetAttribute(gemm_mma_kernel<1, 3>,
                         cudaFuncAttributeMaxDynamicSharedMemorySize, GEMM_SMEM);
    cudaFuncSetAttribute(gemm_mma_kernel<0, 1>,
                         cudaFuncAttributeMaxDynamicSharedMemorySize, GEMM_SMEM);

    // fused Q/K/V projections
    dim3 qkv_grid(CDIM / 128, (BSZ * TSEQ) / 128, 3);
    gemm_mma_kernel<1, 3><<<qkv_grid, 256, GEMM_SMEM>>>(
        x, Wq, Wk, Wv, bq, bk, bv, Qp, Kp, Vp);

    // tensor-core flash attention
    dim3 attn_grid(TSEQ / 64, BSZ * HN);              // (32, 32)
    flash_attn_mma_kernel<<<attn_grid, 128>>>(Qp, Kp, Vp, Ap);

    // output projection
    dim3 o_grid(CDIM / 128, (BSZ * TSEQ) / 128, 1);
    gemm_mma_kernel<0, 1><<<o_grid, 256, GEMM_SMEM>>>(
        Ap, Wo, Wo, Wo, bo, bo, bo, out, out, out);
}

// round 10
// speedup vs baseline: 3.6692x; 1.0831x over previous
#include <cuda_runtime.h>
#include <math_constants.h>
#include <cstdint>

#define BSZ   2
#define TSEQ  2048
#define CDIM  1024
#define HN    16
#define DH    64

// Scratch (allocation-free rule: __device__ globals)
__device__ float g_Q[(size_t)BSZ*HN*TSEQ*DH];   // [B,H,T,D]
__device__ float g_K[(size_t)BSZ*HN*TSEQ*DH];
__device__ float g_V[(size_t)BSZ*HN*TSEQ*DH];
__device__ float g_att[(size_t)BSZ*TSEQ*CDIM];  // [B,T,C] (tf32-rounded)
__device__ float g_xc[(size_t)BSZ*TSEQ*CDIM];   // x pre-rounded to tf32
__device__ float g_Wc[4][(size_t)CDIM*CDIM];    // Wq,Wk,Wv,Wo pre-rounded

// ---------------------------------------------------------------------------
// helpers
// ---------------------------------------------------------------------------
__device__ __forceinline__ uint32_t smem_u32(const void* p) {
    uint32_t a;
    asm("{ .reg .u64 t; cvta.to.shared.u64 t, %1; cvt.u32.u64 %0, t; }"
        : "=r"(a) : "l"(p));
    return a;
}

__device__ __forceinline__ float fast_exp2(float x) {
    float y;
    asm("ex2.approx.f32 %0, %1;" : "=f"(y) : "f"(x));
    return y;
}

__device__ __forceinline__ float to_tf32(float x) {
    float r;
    asm("cvt.rna.tf32.f32 %0, %1;" : "=f"(r) : "f"(x));
    return r;
}

__device__ __forceinline__ void cp_async16(uint32_t dst, const void* src) {
    asm volatile("cp.async.cg.shared.global [%0], [%1], 16;" :: "r"(dst), "l"(src));
}
__device__ __forceinline__ void cp_commit() {
    asm volatile("cp.async.commit_group;");
}
template <int N>
__device__ __forceinline__ void cp_wait() {
    asm volatile("cp.async.wait_group %0;" :: "n"(N));
}

// pack two f32 into bf16x2: low half <- lo, high half <- hi
__device__ __forceinline__ uint32_t pack_bf16x2(float lo, float hi) {
    uint32_t r;
    asm("cvt.rn.bf16x2.f32 %0, %1, %2;" : "=r"(r) : "f"(hi), "f"(lo));
    return r;
}
__device__ __forceinline__ float bf16lo_f(uint32_t w) { return __uint_as_float(w << 16); }
__device__ __forceinline__ float bf16hi_f(uint32_t w) { return __uint_as_float(w & 0xFFFF0000u); }

// tf32 mma.sync m16n8k8 (legacy tensor path; operands pre-rounded => exact)
__device__ __forceinline__ void mma_tf32(float* d, const uint32_t* a, const uint32_t* b)
{
    asm volatile(
        "mma.sync.aligned.m16n8k8.row.col.f32.tf32.tf32.f32 "
        "{%0,%1,%2,%3}, {%4,%5,%6,%7}, {%8,%9}, {%0,%1,%2,%3};"
        : "+f"(d[0]), "+f"(d[1]), "+f"(d[2]), "+f"(d[3])
        : "r"(a[0]), "r"(a[1]), "r"(a[2]), "r"(a[3]),
          "r"(b[0]), "r"(b[1]));
}

// bf16 mma.sync m16n8k16
__device__ __forceinline__ void mma_bf16(float* d, const uint32_t* a, uint32_t b0, uint32_t b1)
{
    asm volatile(
        "mma.sync.aligned.m16n8k16.row.col.f32.bf16.bf16.f32 "
        "{%0,%1,%2,%3}, {%4,%5,%6,%7}, {%8,%9}, {%0,%1,%2,%3};"
        : "+f"(d[0]), "+f"(d[1]), "+f"(d[2]), "+f"(d[3])
        : "r"(a[0]), "r"(a[1]), "r"(a[2]), "r"(a[3]),
          "r"(b0), "r"(b1));
}

// ---------------------------------------------------------------------------
// tf32 pre-conversion pass: x + 4 weight matrices, RNA-rounded once per call.
// Grid (4096, 5): y=0 -> x (4M floats), y=1..4 -> W (1M floats each).
// ---------------------------------------------------------------------------
__global__ __launch_bounds__(256)
void cvt_tf32_kernel(const float* __restrict__ x,
                     const float* __restrict__ Wq, const float* __restrict__ Wk,
                     const float* __restrict__ Wv, const float* __restrict__ Wo)
{
    const int y = blockIdx.y;
    const float* src;
    float* dst;
    int n4;
    if (y == 0)      { src = x;  dst = g_xc;    n4 = BSZ * TSEQ * CDIM / 4; }
    else if (y == 1) { src = Wq; dst = g_Wc[0]; n4 = CDIM * CDIM / 4; }
    else if (y == 2) { src = Wk; dst = g_Wc[1]; n4 = CDIM * CDIM / 4; }
    else if (y == 3) { src = Wv; dst = g_Wc[2]; n4 = CDIM * CDIM / 4; }
    else             { src = Wo; dst = g_Wc[3]; n4 = CDIM * CDIM / 4; }

    const int i = blockIdx.x * blockDim.x + threadIdx.x;
    if (i < n4) {
        float4 v = ((const float4*)src)[i];
        v.x = to_tf32(v.x); v.y = to_tf32(v.y);
        v.z = to_tf32(v.z); v.w = to_tf32(v.w);
        ((float4*)dst)[i] = v;
    }
}

// ---------------------------------------------------------------------------
// tf32 tensor-core GEMM-NT, cp.async double-buffered, 2 CTAs/SM:
//   out[M,N] = A[M,K] @ W[N,K]^T + bias,  M=4096, N=K=1024
// Inputs MUST be pre-rounded to tf32 (mma truncation is then exact).
// CTA tile 128x128, 8 warps x (64x32) micro-grid of m16n8k8, K-chunk 32.
// ---------------------------------------------------------------------------
#define GPAD 36
#define GEMM_SMEM (4 * 128 * GPAD * 4)   // 2 buffers x (As + Bs) = 73728 B

template <int MODE, int NMAT>
__global__ __launch_bounds__(256, 2)
void gemm_mma_kernel(const float* __restrict__ A,
                     const float* __restrict__ W0, const float* __restrict__ W1,
                     const float* __restrict__ W2,
                     const float* __restrict__ b0, const float* __restrict__ b1,
                     const float* __restrict__ b2,
                     float* __restrict__ o0, float* __restrict__ o1,
                     float* __restrict__ o2)
{
    extern __shared__ float smem[];
    float (*As)[128][GPAD] = (float (*)[128][GPAD])(smem);
    float (*Bs)[128][GPAD] = (float (*)[128][GPAD])(smem + 2 * 128 * GPAD);
    const uint32_t smem_base = smem_u32(smem);

    const int z = (NMAT == 3) ? (int)blockIdx.z : 0;
    const float* __restrict__ W    = (z == 0) ? W0 : (z == 1 ? W1 : W2);
    const float* __restrict__ bias = (z == 0) ? b0 : (z == 1 ? b1 : b2);
    float* __restrict__ out        = (z == 0) ? o0 : (z == 1 ? o1 : o2);

    const int tid  = threadIdx.x;
    const int wid  = tid >> 5;
    const int lane = tid & 31;
    const int gID  = lane >> 2;
    const int tig  = lane & 3;
    const int n0 = blockIdx.x * 128;
    const int m0 = blockIdx.y * 128;
    const int wm = (wid >> 2) * 64;
    const int wn = (wid & 3) * 32;

    float acc[4][4][4];
#pragma unroll
    for (int mt = 0; mt < 4; ++mt)
#pragma unroll
        for (int nt = 0; nt < 4; ++nt)
#pragma unroll
            for (int r = 0; r < 4; ++r) acc[mt][nt][r] = 0.f;

    // async copy of one 128x32 chunk of A and W into buffer `buf`
    auto issue = [&](int buf, int k0) {
#pragma unroll
        for (int i = 0; i < 4; ++i) {
            const int idx = tid + i * 256;
            const int row = idx >> 3;
            const int q4  = (idx & 7) * 4;
            const uint32_t dA = smem_base +
                4u * (uint32_t)((buf * 128 + row) * GPAD + q4);
            const uint32_t dB = smem_base +
                4u * (uint32_t)(2 * 128 * GPAD + (buf * 128 + row) * GPAD + q4);
            cp_async16(dA, A + (size_t)(m0 + row) * CDIM + k0 + q4);
            cp_async16(dB, W + (size_t)(n0 + row) * CDIM + k0 + q4);
        }
        cp_commit();
    };

    issue(0, 0);

    for (int c = 0; c < 32; ++c) {
        const int cur = c & 1;
        if (c + 1 < 32) {
            issue(cur ^ 1, (c + 1) * 32);
            cp_wait<1>();     // chunk c complete, chunk c+1 may be in flight
        } else {
            cp_wait<0>();
        }
        __syncthreads();      // chunk-c data from all threads visible

#pragma unroll
        for (int ks = 0; ks < 4; ++ks) {
            const int kk = ks * 8;
            uint32_t af[4][4];
#pragma unroll
            for (int mt = 0; mt < 4; ++mt) {
                const int r0 = wm + mt * 16 + gID;
                af[mt][0] = __float_as_uint(As[cur][r0    ][kk + tig    ]);
                af[mt][1] = __float_as_uint(As[cur][r0 + 8][kk + tig    ]);
                af[mt][2] = __float_as_uint(As[cur][r0    ][kk + tig + 4]);
                af[mt][3] = __float_as_uint(As[cur][r0 + 8][kk + tig + 4]);
            }
            uint32_t bf[4][2];
#pragma unroll
            for (int nt = 0; nt < 4; ++nt) {
                const int rn = wn + nt * 8 + gID;
                bf[nt][0] = __float_as_uint(Bs[cur][rn][kk + tig    ]);
                bf[nt][1] = __float_as_uint(Bs[cur][rn][kk + tig + 4]);
            }
#pragma unroll
            for (int mt = 0; mt < 4; ++mt)
#pragma unroll
                for (int nt = 0; nt < 4; ++nt)
                    mma_tf32(acc[mt][nt], af[mt], bf[nt]);
        }
        __syncthreads();      // all warps done with buf cur before refill
    }

    // ---- epilogue: +bias, float2 stores
#pragma unroll
    for (int mt = 0; mt < 4; ++mt) {
#pragma unroll
        for (int nt = 0; nt < 4; ++nt) {
            const int mrow0 = m0 + wm + mt * 16 + gID;
            const int mrow1 = mrow0 + 8;
            const int ncol  = n0 + wn + nt * 8 + 2 * tig;
            const float bx = bias[ncol], by = bias[ncol + 1];
            float2 v0, v1;
            v0.x = acc[mt][nt][0] + bx; v0.y = acc[mt][nt][1] + by;
            v1.x = acc[mt][nt][2] + bx; v1.y = acc[mt][nt][3] + by;
            if (MODE == 0) {
                *(float2*)&out[(size_t)mrow0 * CDIM + ncol] = v0;
                *(float2*)&out[(size_t)mrow1 * CDIM + ncol] = v1;
            } else {
                const int h  = ncol >> 6;
                const int dd = ncol & 63;
                const int b0r = mrow0 >> 11, t0r = mrow0 & (TSEQ - 1);
                const int b1r = mrow1 >> 11, t1r = mrow1 & (TSEQ - 1);
                *(float2*)&out[(((size_t)(b0r * HN + h)) * TSEQ + t0r) * DH + dd] = v0;
                *(float2*)&out[(((size_t)(b1r * HN + h)) * TSEQ + t1r) * DH + dd] = v1;
            }
        }
    }
}

// ----------------------------------------------------------------------------
// Tensor-core causal flash attention (bf16 split-3, ~fp32 accurate).
// Block: 128 threads (4 warps). Q-tile 64 (16 rows per warp), KV-tile 64.
// Grid: (T/64, B*H); bx reversed so heavy (long-causal) CTAs launch first.
// Epilogue emits tf32-rounded output so the O-proj GEMM consumes it raw.
// ----------------------------------------------------------------------------
#define KPAD 36

__global__ __launch_bounds__(128)
void flash_attn_mma_kernel(const float* __restrict__ Qg,
                           const float* __restrict__ Kg,
                           const float* __restrict__ Vg,
                           float* __restrict__ att)
{
    __shared__ uint32_t sKhi[64 * KPAD];   // [key][d/2]  bf16x2 (d-pairs)
    __shared__ uint32_t sKlo[64 * KPAD];
    __shared__ uint32_t sVhi[64 * KPAD];   // [d][key/2]  bf16x2 (key-pairs)
    __shared__ uint32_t sVlo[64 * KPAD];

    const int bh  = blockIdx.y;
    const int bx  = gridDim.x - 1 - blockIdx.x;   // heavy blocks first
    const int q0  = bx * 64;
    const int tid = threadIdx.x;
    const int wid = tid >> 5;
    const int lane = tid & 31;
    const int gID = lane >> 2;
    const int tig = lane & 3;

    const int rA = q0 + wid * 16 + gID;
    const int rB = rA + 8;

    const float qscale = 0.125f * 1.4426950408889634f;   // 1/sqrt(D) * log2(e)

    // ---- Q fragments in registers (A-layout m16k16), hi/lo split
    uint32_t qhi[4][4], qlo[4][4];
    {
        const float* QA = Qg + ((size_t)bh * TSEQ + rA) * DH;
        const float* QB = Qg + ((size_t)bh * TSEQ + rB) * DH;
#pragma unroll
        for (int ks = 0; ks < 4; ++ks) {
            const int d0 = 16 * ks + 2 * tig;
            const int d1 = d0 + 8;
            float2 fa0 = *(const float2*)(QA + d0);
            float2 fb0 = *(const float2*)(QB + d0);
            float2 fa1 = *(const float2*)(QA + d1);
            float2 fb1 = *(const float2*)(QB + d1);
            fa0.x *= qscale; fa0.y *= qscale; fb0.x *= qscale; fb0.y *= qscale;
            fa1.x *= qscale; fa1.y *= qscale; fb1.x *= qscale; fb1.y *= qscale;
            uint32_t h;
            h = pack_bf16x2(fa0.x, fa0.y); qhi[ks][0] = h;
            qlo[ks][0] = pack_bf16x2(fa0.x - bf16lo_f(h), fa0.y - bf16hi_f(h));
            h = pack_bf16x2(fb0.x, fb0.y); qhi[ks][1] = h;
            qlo[ks][1] = pack_bf16x2(fb0.x - bf16lo_f(h), fb0.y - bf16hi_f(h));
            h = pack_bf16x2(fa1.x, fa1.y); qhi[ks][2] = h;
            qlo[ks][2] = pack_bf16x2(fa1.x - bf16lo_f(h), fa1.y - bf16hi_f(h));
            h = pack_bf16x2(fb1.x, fb1.y); qhi[ks][3] = h;
            qlo[ks][3] = pack_bf16x2(fb1.x - bf16lo_f(h), fb1.y - bf16hi_f(h));
        }
    }

    float O[8][4];
#pragma unroll
    for (int nt = 0; nt < 8; ++nt)
#pragma unroll
        for (int r = 0; r < 4; ++r) O[nt][r] = 0.f;
    float mA = -1e30f, mB = -1e30f, lA = 0.f, lB = 0.f;

    const int ntiles = bx + 1;

    for (int kt = 0; kt < ntiles; ++kt) {
        const int kbase = kt * 64;
        __syncthreads();

        // ---- stage K: [key][d-pair] bf16x2 hi/lo
        {
            const int key = tid & 63;
            const int dh  = tid >> 6;
            const float* kp = Kg + ((size_t)bh * TSEQ + kbase + key) * DH + dh * 32;
            uint32_t* ph = &sKhi[key * KPAD + dh * 16];
            uint32_t* pl = &sKlo[key * KPAD + dh * 16];
#pragma unroll
            for (int i = 0; i < 8; ++i) {
                float4 v = ((const float4*)kp)[i];
                uint32_t h0 = pack_bf16x2(v.x, v.y);
                uint32_t h1 = pack_bf16x2(v.z, v.w);
                ph[2 * i]     = h0;
                ph[2 * i + 1] = h1;
                pl[2 * i]     = pack_bf16x2(v.x - bf16lo_f(h0), v.y - bf16hi_f(h0));
                pl[2 * i + 1] = pack_bf16x2(v.z - bf16lo_f(h1), v.w - bf16hi_f(h1));
            }
        }
        // ---- stage V transposed: [d][key-pair] bf16x2 hi/lo
        {
            const int p  = tid & 31;
            const int dg = tid >> 5;
            const float* v0 = Vg + ((size_t)bh * TSEQ + kbase + 2 * p) * DH + dg * 16;
            const float* v1 = v0 + DH;
#pragma unroll
            for (int i = 0; i < 4; ++i) {
                float4 a = ((const float4*)v0)[i];
                float4 b = ((const float4*)v1)[i];
                const int d0 = dg * 16 + 4 * i;
                float ae[4] = {a.x, a.y, a.z, a.w};
                float be[4] = {b.x, b.y, b.z, b.w};
#pragma unroll
                for (int e = 0; e < 4; ++e) {
                    uint32_t h = pack_bf16x2(ae[e], be[e]);
                    sVhi[(d0 + e) * KPAD + p] = h;
                    sVlo[(d0 + e) * KPAD + p] =
                        pack_bf16x2(ae[e] - bf16lo_f(h), be[e] - bf16hi_f(h));
                }
            }
        }
        __syncthreads();

        // ---- QK^T: S[16 x 64] per warp
        float S[8][4];
#pragma unroll
        for (int nt = 0; nt < 8; ++nt) {
            float c[4] = {0.f, 0.f, 0.f, 0.f};
            const uint32_t* rh = &sKhi[(8 * nt + gID) * KPAD];
            const uint32_t* rl = &sKlo[(8 * nt + gID) * KPAD];
#pragma unroll
            for (int ks = 0; ks < 4; ++ks) {
                const uint32_t b0h = rh[8 * ks + tig];
                const uint32_t b1h = rh[8 * ks + 4 + tig];
                const uint32_t b0l = rl[8 * ks + tig];
                const uint32_t b1l = rl[8 * ks + 4 + tig];
                mma_bf16(c, qhi[ks], b0h, b1h);
                mma_bf16(c, qhi[ks], b0l, b1l);
                mma_bf16(c, qlo[ks], b0h, b1h);
            }
            S[nt][0] = c[0]; S[nt][1] = c[1]; S[nt][2] = c[2]; S[nt][3] = c[3];
        }

        // ---- causal mask on the diagonal tile
        if (kt == bx) {
#pragma unroll
            for (int nt = 0; nt < 8; ++nt) {
                const int col = kbase + 8 * nt + 2 * tig;
                if (col     > rA) S[nt][0] = -1e30f;
                if (col + 1 > rA) S[nt][1] = -1e30f;
                if (col     > rB) S[nt][2] = -1e30f;
                if (col + 1 > rB) S[nt][3] = -1e30f;
            }
        }

        // ---- online softmax (log2 domain)
        float tmA = -1e30f, tmB = -1e30f;
#pragma unroll
        for (int nt = 0; nt < 8; ++nt) {
            tmA = fmaxf(tmA, fmaxf(S[nt][0], S[nt][1]));
            tmB = fmaxf(tmB, fmaxf(S[nt][2], S[nt][3]));
        }
        tmA = fmaxf(tmA, __shfl_xor_sync(0xffffffffu, tmA, 1));
        tmA = fmaxf(tmA, __shfl_xor_sync(0xffffffffu, tmA, 2));
        tmB = fmaxf(tmB, __shfl_xor_sync(0xffffffffu, tmB, 1));
        tmB = fmaxf(tmB, __shfl_xor_sync(0xffffffffu, tmB, 2));

        const float nmA = fmaxf(mA, tmA);
        const float nmB = fmaxf(mB, tmB);
        const float corrA = fast_exp2(mA - nmA);
        const float corrB = fast_exp2(mB - nmB);
        mA = nmA; mB = nmB;
        lA *= corrA; lB *= corrB;
#pragma unroll
        for (int nt = 0; nt < 8; ++nt) {
            O[nt][0] *= corrA; O[nt][1] *= corrA;
            O[nt][2] *= corrB; O[nt][3] *= corrB;
        }

        uint32_t ph[8][2], pl[8][2];
        float sA = 0.f, sB = 0.f;
#pragma unroll
        for (int nt = 0; nt < 8; ++nt) {
            const float p0 = fast_exp2(S[nt][0] - nmA);
            const float p1 = fast_exp2(S[nt][1] - nmA);
            const float p2 = fast_exp2(S[nt][2] - nmB);
            const float p3 = fast_exp2(S[nt][3] - nmB);
            sA += p0 + p1; sB += p2 + p3;
            uint32_t h;
            h = pack_bf16x2(p0, p1); ph[nt][0] = h;
            pl[nt][0] = pack_bf16x2(p0 - bf16lo_f(h), p1 - bf16hi_f(h));
            h = pack_bf16x2(p2, p3); ph[nt][1] = h;
            pl[nt][1] = pack_bf16x2(p2 - bf16lo_f(h), p3 - bf16hi_f(h));
        }
        sA += __shfl_xor_sync(0xffffffffu, sA, 1);
        sA += __shfl_xor_sync(0xffffffffu, sA, 2);
        sB += __shfl_xor_sync(0xffffffffu, sB, 1);
        sB += __shfl_xor_sync(0xffffffffu, sB, 2);
        lA += sA; lB += sB;

        // ---- PV: O += P @ V
#pragma unroll
        for (int dnt = 0; dnt < 8; ++dnt) {
            const uint32_t* rh = &sVhi[(8 * dnt + gID) * KPAD];
            const uint32_t* rl = &sVlo[(8 * dnt + gID) * KPAD];
#pragma unroll
            for (int ks = 0; ks < 4; ++ks) {
                uint32_t ah[4] = {ph[2 * ks][0], ph[2 * ks][1],
                                  ph[2 * ks + 1][0], ph[2 * ks + 1][1]};
                uint32_t al[4] = {pl[2 * ks][0], pl[2 * ks][1],
                                  pl[2 * ks + 1][0], pl[2 * ks + 1][1]};
                const uint32_t b0h = rh[8 * ks + tig];
                const uint32_t b1h = rh[8 * ks + 4 + tig];
                const uint32_t b0l = rl[8 * ks + tig];
                const uint32_t b1l = rl[8 * ks + 4 + tig];
                mma_bf16(O[dnt], ah, b0h, b1h);
                mma_bf16(O[dnt], ah, b0l, b1l);
                mma_bf16(O[dnt], al, b0h, b1h);
            }
        }
    }

    // ---- epilogue: normalize, tf32-round, store to [B,T,C]
    const float invA = 1.0f / lA;
    const float invB = 1.0f / lB;
    const int b = bh >> 4;
    const int h = bh & 15;
    float* oA = att + ((size_t)(b * TSEQ + rA)) * CDIM + h * DH;
    float* oB = att + ((size_t)(b * TSEQ + rB)) * CDIM + h * DH;
#pragma unroll
    for (int nt = 0; nt < 8; ++nt) {
        const int col = 8 * nt + 2 * tig;
        float2 vA, vB;
        vA.x = to_tf32(O[nt][0] * invA); vA.y = to_tf32(O[nt][1] * invA);
        vB.x = to_tf32(O[nt][2] * invB); vB.y = to_tf32(O[nt][3] * invB);
        *(float2*)(oA + col) = vA;
        *(float2*)(oB + col) = vB;
    }
}

// ----------------------------------------------------------------------------
extern "C" void kernel_launch(void* const* d_in, const int* in_sizes, int n_in,
                              void* d_out, int out_size)
{
    const float* x  = (const float*)d_in[0];
    const float* Wq = (const float*)d_in[1];
    const float* bq = (const float*)d_in[2];
    const float* Wk = (const float*)d_in[3];
    const float* bk = (const float*)d_in[4];
    const float* Wv = (const float*)d_in[5];
    const float* bv = (const float*)d_in[6];
    const float* Wo = (const float*)d_in[7];
    const float* bo = (const float*)d_in[8];
    float* out = (float*)d_out;

    float *Qp, *Kp, *Vp, *Ap, *xc, *wc;
    cudaGetSymbolAddress((void**)&Qp, g_Q);
    cudaGetSymbolAddress((void**)&Kp, g_K);
    cudaGetSymbolAddress((void**)&Vp, g_V);
    cudaGetSymbolAddress((void**)&Ap, g_att);
    cudaGetSymbolAddress((void**)&xc, g_xc);
    cudaGetSymbolAddress((void**)&wc, g_Wc);
    float* Wqc = wc;
    float* Wkc = wc + (size_t)CDIM * CDIM;
    float* Wvc = wc + 2 * (size_t)CDIM * CDIM;
    float* Woc = wc + 3 * (size_t)CDIM * CDIM;

    cudaFuncSetAttribute(gemm_mma_kernel<1, 3>,
                         cudaFuncAttributeMaxDynamicSharedMemorySize, GEMM_SMEM);
    cudaFuncSetAttribute(gemm_mma_kernel<0, 1>,
                         cudaFuncAttributeMaxDynamicSharedMemorySize, GEMM_SMEM);

    // tf32 pre-rounding of x and all weights (once per call, ~12 us)
    dim3 cvt_grid((BSZ * TSEQ * CDIM / 4 + 255) / 256, 5);
    cvt_tf32_kernel<<<cvt_grid, 256>>>(x, Wq, Wk, Wv, Wo);

    // fused Q/K/V projections
    dim3 qkv_grid(CDIM / 128, (BSZ * TSEQ) / 128, 3);
    gemm_mma_kernel<1, 3><<<qkv_grid, 256, GEMM_SMEM>>>(
        xc, Wqc, Wkc, Wvc, bq, bk, bv, Qp, Kp, Vp);

    // tensor-core flash attention
    dim3 attn_grid(TSEQ / 64, BSZ * HN);              // (32, 32)
    flash_attn_mma_kernel<<<attn_grid, 128>>>(Qp, Kp, Vp, Ap);

    // output projection
    dim3 o_grid(CDIM / 128, (BSZ * TSEQ) / 128, 1);
    gemm_mma_kernel<0, 1><<<o_grid, 256, GEMM_SMEM>>>(
        Ap, Woc, Woc, Woc, bo, bo, bo, out, out, out);
}

// round 12
// speedup vs baseline: 4.4318x; 1.2078x over previous
#include <cuda_runtime.h>
#include <math_constants.h>
#include <cstdint>

#define BSZ   2
#define TSEQ  2048
#define CDIM  1024
#define HN    16
#define DH    64

// Scratch (allocation-free rule: __device__ globals)
__device__ float g_Q[(size_t)BSZ*HN*TSEQ*DH];   // [B,H,T,D]
__device__ float g_K[(size_t)BSZ*HN*TSEQ*DH];
__device__ float g_V[(size_t)BSZ*HN*TSEQ*DH];
__device__ float g_att[(size_t)BSZ*TSEQ*CDIM];  // [B,T,C] (tf32-rounded)
__device__ float g_xc[(size_t)BSZ*TSEQ*CDIM];   // x pre-rounded to tf32
__device__ float g_Wc[4][(size_t)CDIM*CDIM];    // Wq,Wk,Wv,Wo pre-rounded

// packed bf16x2 hi/lo buffers (produced once per call by pack_kernel)
#define NWORD_QK ((size_t)BSZ*HN*TSEQ*(DH/2))
#define NWORD_V  ((size_t)BSZ*HN*DH*(TSEQ/2))
__device__ uint32_t g_Qh[NWORD_QK], g_Ql[NWORD_QK];   // [bh][t][d/2], qscale folded
__device__ uint32_t g_Kh[NWORD_QK], g_Kl[NWORD_QK];   // [bh][t][d/2]
__device__ uint32_t g_Vh[NWORD_V],  g_Vl[NWORD_V];    // [bh][d][t/2] (transposed)

// ---------------------------------------------------------------------------
// helpers
// ---------------------------------------------------------------------------
__device__ __forceinline__ uint32_t smem_u32(const void* p) {
    uint32_t a;
    asm("{ .reg .u64 t; cvta.to.shared.u64 t, %1; cvt.u32.u64 %0, t; }"
        : "=r"(a) : "l"(p));
    return a;
}

__device__ __forceinline__ float fast_exp2(float x) {
    float y;
    asm("ex2.approx.f32 %0, %1;" : "=f"(y) : "f"(x));
    return y;
}

__device__ __forceinline__ float to_tf32(float x) {
    float r;
    asm("cvt.rna.tf32.f32 %0, %1;" : "=f"(r) : "f"(x));
    return r;
}

__device__ __forceinline__ void cp_async16(uint32_t dst, const void* src) {
    asm volatile("cp.async.cg.shared.global [%0], [%1], 16;" :: "r"(dst), "l"(src));
}
__device__ __forceinline__ void cp_commit() {
    asm volatile("cp.async.commit_group;");
}
template <int N>
__device__ __forceinline__ void cp_wait() {
    asm volatile("cp.async.wait_group %0;" :: "n"(N));
}

// pack two f32 into bf16x2: low half <- lo, high half <- hi
__device__ __forceinline__ uint32_t pack_bf16x2(float lo, float hi) {
    uint32_t r;
    asm("cvt.rn.bf16x2.f32 %0, %1, %2;" : "=r"(r) : "f"(hi), "f"(lo));
    return r;
}
__device__ __forceinline__ float bf16lo_f(uint32_t w) { return __uint_as_float(w << 16); }
__device__ __forceinline__ float bf16hi_f(uint32_t w) { return __uint_as_float(w & 0xFFFF0000u); }

// tf32 mma.sync m16n8k8 (non-volatile: pure computation, lets ptxas hoist loads)
__device__ __forceinline__ void mma_tf32(float* d, const uint32_t* a, const uint32_t* b)
{
    asm("mma.sync.aligned.m16n8k8.row.col.f32.tf32.tf32.f32 "
        "{%0,%1,%2,%3}, {%4,%5,%6,%7}, {%8,%9}, {%0,%1,%2,%3};"
        : "+f"(d[0]), "+f"(d[1]), "+f"(d[2]), "+f"(d[3])
        : "r"(a[0]), "r"(a[1]), "r"(a[2]), "r"(a[3]),
          "r"(b[0]), "r"(b[1]));
}

// bf16 mma.sync m16n8k16 (non-volatile)
__device__ __forceinline__ void mma_bf16(float* d, const uint32_t* a, uint32_t b0, uint32_t b1)
{
    asm("mma.sync.aligned.m16n8k16.row.col.f32.bf16.bf16.f32 "
        "{%0,%1,%2,%3}, {%4,%5,%6,%7}, {%8,%9}, {%0,%1,%2,%3};"
        : "+f"(d[0]), "+f"(d[1]), "+f"(d[2]), "+f"(d[3])
        : "r"(a[0]), "r"(a[1]), "r"(a[2]), "r"(a[3]),
          "r"(b0), "r"(b1));
}

// ---------------------------------------------------------------------------
// tf32 pre-conversion pass: x + 4 weight matrices, RNA-rounded once per call.
// ---------------------------------------------------------------------------
__global__ __launch_bounds__(256)
void cvt_tf32_kernel(const float* __restrict__ x,
                     const float* __restrict__ Wq, const float* __restrict__ Wk,
                     const float* __restrict__ Wv, const float* __restrict__ Wo)
{
    const int y = blockIdx.y;
    const float* src;
    float* dst;
    int n4;
    if (y == 0)      { src = x;  dst = g_xc;    n4 = BSZ * TSEQ * CDIM / 4; }
    else if (y == 1) { src = Wq; dst = g_Wc[0]; n4 = CDIM * CDIM / 4; }
    else if (y == 2) { src = Wk; dst = g_Wc[1]; n4 = CDIM * CDIM / 4; }
    else if (y == 3) { src = Wv; dst = g_Wc[2]; n4 = CDIM * CDIM / 4; }
    else             { src = Wo; dst = g_Wc[3]; n4 = CDIM * CDIM / 4; }

    const int i = blockIdx.x * blockDim.x + threadIdx.x;
    if (i < n4) {
        float4 v = ((const float4*)src)[i];
        v.x = to_tf32(v.x); v.y = to_tf32(v.y);
        v.z = to_tf32(v.z); v.w = to_tf32(v.w);
        ((float4*)dst)[i] = v;
    }
}

// ---------------------------------------------------------------------------
// Pack pass: bf16 hi/lo split of Q (qscale folded), K, and transposed V.
// Grid (T/64, B*H), 256 threads. Runs after the QKV GEMM.
// ---------------------------------------------------------------------------
__global__ __launch_bounds__(256)
void pack_kernel()
{
    __shared__ float sv[64][68];   // V tile [t][d]; 68: float4-aligned rows

    const int bh = blockIdx.y;
    const int t0 = blockIdx.x * 64;
    const int tid = threadIdx.x;
    const float qscale = 0.125f * 1.4426950408889634f;   // 1/sqrt(D)*log2(e)

    // load V tile [t0..t0+63][0..63] (coalesced float4)
#pragma unroll
    for (int i = 0; i < 4; ++i) {
        const int idx = tid + i * 256;        // 0..1023 float4 slots
        const int row = idx >> 4;
        const int c4  = (idx & 15) * 4;
        *(float4*)&sv[row][c4] =
            *(const float4*)&g_V[((size_t)bh * TSEQ + t0 + row) * DH + c4];
    }

    // Q and K: elementwise pair packing (no transpose)
#pragma unroll
    for (int i = 0; i < 8; ++i) {
        const int idx = tid + i * 256;        // 0..2047 (row, pair)
        const int row = idx >> 5;
        const int p   = idx & 31;
        const size_t src = ((size_t)bh * TSEQ + t0 + row) * DH + 2 * p;
        const size_t dst = ((size_t)bh * TSEQ + t0 + row) * (DH / 2) + p;

        float2 q = *(const float2*)&g_Q[src];
        q.x *= qscale; q.y *= qscale;
        uint32_t qh = pack_bf16x2(q.x, q.y);
        g_Qh[dst] = qh;
        g_Ql[dst] = pack_bf16x2(q.x - bf16lo_f(qh), q.y - bf16hi_f(qh));

        float2 k = *(const float2*)&g_K[src];
        uint32_t kh = pack_bf16x2(k.x, k.y);
        g_Kh[dst] = kh;
        g_Kl[dst] = pack_bf16x2(k.x - bf16lo_f(kh), k.y - bf16hi_f(kh));
    }
    __syncthreads();

    // V transposed: word(d, p) = pack(V[t0+2p][d], V[t0+2p+1][d])
#pragma unroll
    for (int i = 0; i < 8; ++i) {
        const int idx = tid + i * 256;        // 0..2047 (d, pair)
        const int d = idx >> 5;
        const int p = idx & 31;
        const float v0 = sv[2 * p][d];
        const float v1 = sv[2 * p + 1][d];
        const uint32_t h = pack_bf16x2(v0, v1);
        const size_t dst = ((size_t)bh * DH + d) * (TSEQ / 2) + t0 / 2 + p;
        g_Vh[dst] = h;
        g_Vl[dst] = pack_bf16x2(v0 - bf16lo_f(h), v1 - bf16hi_f(h));
    }
}

// ---------------------------------------------------------------------------
// tf32 tensor-core GEMM-NT, cp.async double-buffered, 2 CTAs/SM (proven R9).
// ---------------------------------------------------------------------------
#define GPAD 36
#define GEMM_SMEM (4 * 128 * GPAD * 4)   // 73728 B

template <int MODE, int NMAT>
__global__ __launch_bounds__(256, 2)
void gemm_mma_kernel(const float* __restrict__ A,
                     const float* __restrict__ W0, const float* __restrict__ W1,
                     const float* __restrict__ W2,
                     const float* __restrict__ b0, const float* __restrict__ b1,
                     const float* __restrict__ b2,
                     float* __restrict__ o0, float* __restrict__ o1,
                     float* __restrict__ o2)
{
    extern __shared__ float smem[];
    float (*As)[128][GPAD] = (float (*)[128][GPAD])(smem);
    float (*Bs)[128][GPAD] = (float (*)[128][GPAD])(smem + 2 * 128 * GPAD);
    const uint32_t smem_base = smem_u32(smem);

    const int z = (NMAT == 3) ? (int)blockIdx.z : 0;
    const float* __restrict__ W    = (z == 0) ? W0 : (z == 1 ? W1 : W2);
    const float* __restrict__ bias = (z == 0) ? b0 : (z == 1 ? b1 : b2);
    float* __restrict__ out        = (z == 0) ? o0 : (z == 1 ? o1 : o2);

    const int tid  = threadIdx.x;
    const int wid  = tid >> 5;
    const int lane = tid & 31;
    const int gID  = lane >> 2;
    const int tig  = lane & 3;
    const int n0 = blockIdx.x * 128;
    const int m0 = blockIdx.y * 128;
    const int wm = (wid >> 2) * 64;
    const int wn = (wid & 3) * 32;

    float acc[4][4][4];
#pragma unroll
    for (int mt = 0; mt < 4; ++mt)
#pragma unroll
        for (int nt = 0; nt < 4; ++nt)
#pragma unroll
            for (int r = 0; r < 4; ++r) acc[mt][nt][r] = 0.f;

    auto issue = [&](int buf, int k0) {
#pragma unroll
        for (int i = 0; i < 4; ++i) {
            const int idx = tid + i * 256;
            const int row = idx >> 3;
            const int q4  = (idx & 7) * 4;
            const uint32_t dA = smem_base +
                4u * (uint32_t)((buf * 128 + row) * GPAD + q4);
            const uint32_t dB = smem_base +
                4u * (uint32_t)(2 * 128 * GPAD + (buf * 128 + row) * GPAD + q4);
            cp_async16(dA, A + (size_t)(m0 + row) * CDIM + k0 + q4);
            cp_async16(dB, W + (size_t)(n0 + row) * CDIM + k0 + q4);
        }
        cp_commit();
    };

    issue(0, 0);

    for (int c = 0; c < 32; ++c) {
        const int cur = c & 1;
        if (c + 1 < 32) {
            issue(cur ^ 1, (c + 1) * 32);
            cp_wait<1>();
        } else {
            cp_wait<0>();
        }
        __syncthreads();

#pragma unroll
        for (int ks = 0; ks < 4; ++ks) {
            const int kk = ks * 8;
            uint32_t af[4][4];
#pragma unroll
            for (int mt = 0; mt < 4; ++mt) {
                const int r0 = wm + mt * 16 + gID;
                af[mt][0] = __float_as_uint(As[cur][r0    ][kk + tig    ]);
                af[mt][1] = __float_as_uint(As[cur][r0 + 8][kk + tig    ]);
                af[mt][2] = __float_as_uint(As[cur][r0    ][kk + tig + 4]);
                af[mt][3] = __float_as_uint(As[cur][r0 + 8][kk + tig + 4]);
            }
            uint32_t bf[4][2];
#pragma unroll
            for (int nt = 0; nt < 4; ++nt) {
                const int rn = wn + nt * 8 + gID;
                bf[nt][0] = __float_as_uint(Bs[cur][rn][kk + tig    ]);
                bf[nt][1] = __float_as_uint(Bs[cur][rn][kk + tig + 4]);
            }
#pragma unroll
            for (int mt = 0; mt < 4; ++mt)
#pragma unroll
                for (int nt = 0; nt < 4; ++nt)
                    mma_tf32(acc[mt][nt], af[mt], bf[nt]);
        }
        __syncthreads();
    }

#pragma unroll
    for (int mt = 0; mt < 4; ++mt) {
#pragma unroll
        for (int nt = 0; nt < 4; ++nt) {
            const int mrow0 = m0 + wm + mt * 16 + gID;
            const int mrow1 = mrow0 + 8;
            const int ncol  = n0 + wn + nt * 8 + 2 * tig;
            const float bx = bias[ncol], by = bias[ncol + 1];
            float2 v0, v1;
            v0.x = acc[mt][nt][0] + bx; v0.y = acc[mt][nt][1] + by;
            v1.x = acc[mt][nt][2] + bx; v1.y = acc[mt][nt][3] + by;
            if (MODE == 0) {
                *(float2*)&out[(size_t)mrow0 * CDIM + ncol] = v0;
                *(float2*)&out[(size_t)mrow1 * CDIM + ncol] = v1;
            } else {
                const int h  = ncol >> 6;
                const int dd = ncol & 63;
                const int b0r = mrow0 >> 11, t0r = mrow0 & (TSEQ - 1);
                const int b1r = mrow1 >> 11, t1r = mrow1 & (TSEQ - 1);
                *(float2*)&out[(((size_t)(b0r * HN + h)) * TSEQ + t0r) * DH + dd] = v0;
                *(float2*)&out[(((size_t)(b1r * HN + h)) * TSEQ + t1r) * DH + dd] = v1;
            }
        }
    }
}

// ----------------------------------------------------------------------------
// Tensor-core causal flash attention (bf16 split-3, ~fp32 accurate).
// K/V/Q pre-packed to bf16 hi/lo by pack_kernel; staging = pure cp.async.
// Block: 128 threads (4 warps). Q-tile 64, KV-tile 64. Grid: (T/64, B*H),
// bx reversed so heavy CTAs launch first.
// ----------------------------------------------------------------------------
#define KPAD 36

__global__ __launch_bounds__(128)
void flash_attn_mma_kernel(float* __restrict__ att)
{
    __shared__ uint32_t sKhi[64 * KPAD];   // [key][d/2]  bf16x2
    __shared__ uint32_t sKlo[64 * KPAD];
    __shared__ uint32_t sVhi[64 * KPAD];   // [d][key/2]  bf16x2
    __shared__ uint32_t sVlo[64 * KPAD];

    const int bh  = blockIdx.y;
    const int bx  = gridDim.x - 1 - blockIdx.x;
    const int q0  = bx * 64;
    const int tid = threadIdx.x;
    const int wid = tid >> 5;
    const int lane = tid & 31;
    const int gID = lane >> 2;
    const int tig = lane & 3;

    const int rA = q0 + wid * 16 + gID;
    const int rB = rA + 8;

    const uint32_t sKh_b = smem_u32(sKhi);
    const uint32_t sKl_b = smem_u32(sKlo);
    const uint32_t sVh_b = smem_u32(sVhi);
    const uint32_t sVl_b = smem_u32(sVlo);

    // ---- Q fragments from packed buffers (qscale already folded)
    uint32_t qhi[4][4], qlo[4][4];
    {
        const uint32_t* QhA = g_Qh + ((size_t)bh * TSEQ + rA) * (DH / 2);
        const uint32_t* QhB = g_Qh + ((size_t)bh * TSEQ + rB) * (DH / 2);
        const uint32_t* QlA = g_Ql + ((size_t)bh * TSEQ + rA) * (DH / 2);
        const uint32_t* QlB = g_Ql + ((size_t)bh * TSEQ + rB) * (DH / 2);
#pragma unroll
        for (int ks = 0; ks < 4; ++ks) {
            const int p = 8 * ks + tig;
            qhi[ks][0] = QhA[p];     qhi[ks][1] = QhB[p];
            qhi[ks][2] = QhA[p + 4]; qhi[ks][3] = QhB[p + 4];
            qlo[ks][0] = QlA[p];     qlo[ks][1] = QlB[p];
            qlo[ks][2] = QlA[p + 4]; qlo[ks][3] = QlB[p + 4];
        }
    }

    float O[8][4];
#pragma unroll
    for (int nt = 0; nt < 8; ++nt)
#pragma unroll
        for (int r = 0; r < 4; ++r) O[nt][r] = 0.f;
    float mA = -1e30f, mB = -1e30f, lA = 0.f, lB = 0.f;

    const int ntiles = bx + 1;

    for (int kt = 0; kt < ntiles; ++kt) {
        const int kbase = kt * 64;
        __syncthreads();   // previous tile fully consumed

        // ---- stage K/V via cp.async (4 x 16B per array per thread)
#pragma unroll
        for (int i = 0; i < 4; ++i) {
            const int idx = tid + i * 128;      // 0..511
            const int row = idx >> 3;           // 0..63 (key for K, d for V)
            const int c   = idx & 7;            // 16B chunk within 128B row
            const uint32_t off = 4u * (uint32_t)(row * KPAD + c * 4);
            const size_t srcK = ((size_t)bh * TSEQ + kbase + row) * (DH / 2) + c * 4;
            const size_t srcV = ((size_t)bh * DH + row) * (TSEQ / 2) + kbase / 2 + c * 4;
            cp_async16(sKh_b + off, g_Kh + srcK);
            cp_async16(sKl_b + off, g_Kl + srcK);
            cp_async16(sVh_b + off, g_Vh + srcV);
            cp_async16(sVl_b + off, g_Vl + srcV);
        }
        cp_commit();
        cp_wait<0>();
        __syncthreads();

        // ---- QK^T: S[16 x 64] per warp
        float S[8][4];
#pragma unroll
        for (int nt = 0; nt < 8; ++nt) {
            float c[4] = {0.f, 0.f, 0.f, 0.f};
            const uint32_t* rh = &sKhi[(8 * nt + gID) * KPAD];
            const uint32_t* rl = &sKlo[(8 * nt + gID) * KPAD];
#pragma unroll
            for (int ks = 0; ks < 4; ++ks) {
                const uint32_t b0h = rh[8 * ks + tig];
                const uint32_t b1h = rh[8 * ks + 4 + tig];
                const uint32_t b0l = rl[8 * ks + tig];
                const uint32_t b1l = rl[8 * ks + 4 + tig];
                mma_bf16(c, qhi[ks], b0h, b1h);
                mma_bf16(c, qhi[ks], b0l, b1l);
                mma_bf16(c, qlo[ks], b0h, b1h);
            }
            S[nt][0] = c[0]; S[nt][1] = c[1]; S[nt][2] = c[2]; S[nt][3] = c[3];
        }

        // ---- causal mask on the diagonal tile
        if (kt == bx) {
#pragma unroll
            for (int nt = 0; nt < 8; ++nt) {
                const int col = kbase + 8 * nt + 2 * tig;
                if (col     > rA) S[nt][0] = -1e30f;
                if (col + 1 > rA) S[nt][1] = -1e30f;
                if (col     > rB) S[nt][2] = -1e30f;
                if (col + 1 > rB) S[nt][3] = -1e30f;
            }
        }

        // ---- online softmax (log2 domain)
        float tmA = -1e30f, tmB = -1e30f;
#pragma unroll
        for (int nt = 0; nt < 8; ++nt) {
            tmA = fmaxf(tmA, fmaxf(S[nt][0], S[nt][1]));
            tmB = fmaxf(tmB, fmaxf(S[nt][2], S[nt][3]));
        }
        tmA = fmaxf(tmA, __shfl_xor_sync(0xffffffffu, tmA, 1));
        tmA = fmaxf(tmA, __shfl_xor_sync(0xffffffffu, tmA, 2));
        tmB = fmaxf(tmB, __shfl_xor_sync(0xffffffffu, tmB, 1));
        tmB = fmaxf(tmB, __shfl_xor_sync(0xffffffffu, tmB, 2));

        const float nmA = fmaxf(mA, tmA);
        const float nmB = fmaxf(mB, tmB);
        const float corrA = fast_exp2(mA - nmA);
        const float corrB = fast_exp2(mB - nmB);
        mA = nmA; mB = nmB;
        lA *= corrA; lB *= corrB;
#pragma unroll
        for (int nt = 0; nt < 8; ++nt) {
            O[nt][0] *= corrA; O[nt][1] *= corrA;
            O[nt][2] *= corrB; O[nt][3] *= corrB;
        }

        uint32_t ph[8][2], pl[8][2];
        float sA = 0.f, sB = 0.f;
#pragma unroll
        for (int nt = 0; nt < 8; ++nt) {
            const float p0 = fast_exp2(S[nt][0] - nmA);
            const float p1 = fast_exp2(S[nt][1] - nmA);
            const float p2 = fast_exp2(S[nt][2] - nmB);
            const float p3 = fast_exp2(S[nt][3] - nmB);
            sA += p0 + p1; sB += p2 + p3;
            uint32_t h;
            h = pack_bf16x2(p0, p1); ph[nt][0] = h;
            pl[nt][0] = pack_bf16x2(p0 - bf16lo_f(h), p1 - bf16hi_f(h));
            h = pack_bf16x2(p2, p3); ph[nt][1] = h;
            pl[nt][1] = pack_bf16x2(p2 - bf16lo_f(h), p3 - bf16hi_f(h));
        }
        sA += __shfl_xor_sync(0xffffffffu, sA, 1);
        sA += __shfl_xor_sync(0xffffffffu, sA, 2);
        sB += __shfl_xor_sync(0xffffffffu, sB, 1);
        sB += __shfl_xor_sync(0xffffffffu, sB, 2);
        lA += sA; lB += sB;

        // ---- PV: O += P @ V
#pragma unroll
        for (int dnt = 0; dnt < 8; ++dnt) {
            const uint32_t* rh = &sVhi[(8 * dnt + gID) * KPAD];
            const uint32_t* rl = &sVlo[(8 * dnt + gID) * KPAD];
#pragma unroll
            for (int ks = 0; ks < 4; ++ks) {
                uint32_t ah[4] = {ph[2 * ks][0], ph[2 * ks][1],
                                  ph[2 * ks + 1][0], ph[2 * ks + 1][1]};
                uint32_t al[4] = {pl[2 * ks][0], pl[2 * ks][1],
                                  pl[2 * ks + 1][0], pl[2 * ks + 1][1]};
                const uint32_t b0h = rh[8 * ks + tig];
                const uint32_t b1h = rh[8 * ks + 4 + tig];
                const uint32_t b0l = rl[8 * ks + tig];
                const uint32_t b1l = rl[8 * ks + 4 + tig];
                mma_bf16(O[dnt], ah, b0h, b1h);
                mma_bf16(O[dnt], ah, b0l, b1l);
                mma_bf16(O[dnt], al, b0h, b1h);
            }
        }
    }

    // ---- epilogue: normalize, tf32-round, store to [B,T,C]
    const float invA = 1.0f / lA;
    const float invB = 1.0f / lB;
    const int b = bh >> 4;
    const int h = bh & 15;
    float* oA = att + ((size_t)(b * TSEQ + rA)) * CDIM + h * DH;
    float* oB = att + ((size_t)(b * TSEQ + rB)) * CDIM + h * DH;
#pragma unroll
    for (int nt = 0; nt < 8; ++nt) {
        const int col = 8 * nt + 2 * tig;
        float2 vA, vB;
        vA.x = to_tf32(O[nt][0] * invA); vA.y = to_tf32(O[nt][1] * invA);
        vB.x = to_tf32(O[nt][2] * invB); vB.y = to_tf32(O[nt][3] * invB);
        *(float2*)(oA + col) = vA;
        *(float2*)(oB + col) = vB;
    }
}

// ----------------------------------------------------------------------------
extern "C" void kernel_launch(void* const* d_in, const int* in_sizes, int n_in,
                              void* d_out, int out_size)
{
    const float* x  = (const float*)d_in[0];
    const float* Wq = (const float*)d_in[1];
    const float* bq = (const float*)d_in[2];
    const float* Wk = (const float*)d_in[3];
    const float* bk = (const float*)d_in[4];
    const float* Wv = (const float*)d_in[5];
    const float* bv = (const float*)d_in[6];
    const float* Wo = (const float*)d_in[7];
    const float* bo = (const float*)d_in[8];
    float* out = (float*)d_out;

    float *Qp, *Kp, *Vp, *Ap, *xc, *wc;
    cudaGetSymbolAddress((void**)&Qp, g_Q);
    cudaGetSymbolAddress((void**)&Kp, g_K);
    cudaGetSymbolAddress((void**)&Vp, g_V);
    cudaGetSymbolAddress((void**)&Ap, g_att);
    cudaGetSymbolAddress((void**)&xc, g_xc);
    cudaGetSymbolAddress((void**)&wc, g_Wc);
    float* Wqc = wc;
    float* Wkc = wc + (size_t)CDIM * CDIM;
    float* Wvc = wc + 2 * (size_t)CDIM * CDIM;
    float* Woc = wc + 3 * (size_t)CDIM * CDIM;

    cudaFuncSetAttribute(gemm_mma_kernel<1, 3>,
                         cudaFuncAttributeMaxDynamicSharedMemorySize, GEMM_SMEM);
    cudaFuncSetAttribute(gemm_mma_kernel<0, 1>,
                         cudaFuncAttributeMaxDynamicSharedMemorySize, GEMM_SMEM);

    // tf32 pre-rounding of x and all weights
    dim3 cvt_grid((BSZ * TSEQ * CDIM / 4 + 255) / 256, 5);
    cvt_tf32_kernel<<<cvt_grid, 256>>>(x, Wq, Wk, Wv, Wo);

    // fused Q/K/V projections
    dim3 qkv_grid(CDIM / 128, (BSZ * TSEQ) / 128, 3);
    gemm_mma_kernel<1, 3><<<qkv_grid, 256, GEMM_SMEM>>>(
        xc, Wqc, Wkc, Wvc, bq, bk, bv, Qp, Kp, Vp);

    // bf16 hi/lo pack of Q (scaled), K, V (transposed)
    dim3 pack_grid(TSEQ / 64, BSZ * HN);
    pack_kernel<<<pack_grid, 256>>>();

    // tensor-core flash attention
    dim3 attn_grid(TSEQ / 64, BSZ * HN);              // (32, 32)
    flash_attn_mma_kernel<<<attn_grid, 128>>>(Ap);

    // output projection
    dim3 o_grid(CDIM / 128, (BSZ * TSEQ) / 128, 1);
    gemm_mma_kernel<0, 1><<<o_grid, 256, GEMM_SMEM>>>(
        Ap, Woc, Woc, Woc, bo, bo, bo, out, out, out);
}

// round 13
// speedup vs baseline: 4.5642x; 1.0299x over previous
#include <cuda_runtime.h>
#include <math_constants.h>
#include <cstdint>

#define BSZ   2
#define TSEQ  2048
#define CDIM  1024
#define HN    16
#define DH    64

// Scratch (allocation-free rule: __device__ globals)
__device__ float g_Q[(size_t)BSZ*HN*TSEQ*DH];   // [B,H,T,D]
__device__ float g_K[(size_t)BSZ*HN*TSEQ*DH];
__device__ float g_V[(size_t)BSZ*HN*TSEQ*DH];
__device__ float g_att[(size_t)BSZ*TSEQ*CDIM];  // [B,T,C] (tf32-rounded)
__device__ float g_xc[(size_t)BSZ*TSEQ*CDIM];   // x pre-rounded to tf32
__device__ float g_Wc[4][(size_t)CDIM*CDIM];    // Wq,Wk,Wv,Wo pre-rounded

// packed bf16x2 hi/lo buffers (produced once per call by pack_kernel)
#define NWORD_QK ((size_t)BSZ*HN*TSEQ*(DH/2))
#define NWORD_V  ((size_t)BSZ*HN*DH*(TSEQ/2))
__device__ uint32_t g_Qh[NWORD_QK], g_Ql[NWORD_QK];   // [bh][t][d/2], qscale folded
__device__ uint32_t g_Kh[NWORD_QK], g_Kl[NWORD_QK];   // [bh][t][d/2]
__device__ uint32_t g_Vh[NWORD_V],  g_Vl[NWORD_V];    // [bh][d][t/2] (transposed)

// ---------------------------------------------------------------------------
// helpers
// ---------------------------------------------------------------------------
__device__ __forceinline__ uint32_t smem_u32(const void* p) {
    uint32_t a;
    asm("{ .reg .u64 t; cvta.to.shared.u64 t, %1; cvt.u32.u64 %0, t; }"
        : "=r"(a) : "l"(p));
    return a;
}

__device__ __forceinline__ float fast_exp2(float x) {
    float y;
    asm("ex2.approx.f32 %0, %1;" : "=f"(y) : "f"(x));
    return y;
}

__device__ __forceinline__ float to_tf32(float x) {
    float r;
    asm("cvt.rna.tf32.f32 %0, %1;" : "=f"(r) : "f"(x));
    return r;
}

__device__ __forceinline__ void cp_async16(uint32_t dst, const void* src) {
    asm volatile("cp.async.cg.shared.global [%0], [%1], 16;" :: "r"(dst), "l"(src));
}
__device__ __forceinline__ void cp_commit() {
    asm volatile("cp.async.commit_group;");
}
template <int N>
__device__ __forceinline__ void cp_wait() {
    asm volatile("cp.async.wait_group %0;" :: "n"(N));
}

// pack two f32 into bf16x2: low half <- lo, high half <- hi
__device__ __forceinline__ uint32_t pack_bf16x2(float lo, float hi) {
    uint32_t r;
    asm("cvt.rn.bf16x2.f32 %0, %1, %2;" : "=r"(r) : "f"(hi), "f"(lo));
    return r;
}
__device__ __forceinline__ float bf16lo_f(uint32_t w) { return __uint_as_float(w << 16); }
__device__ __forceinline__ float bf16hi_f(uint32_t w) { return __uint_as_float(w & 0xFFFF0000u); }

// tf32 mma.sync m16n8k8 (non-volatile: pure computation, lets ptxas hoist loads)
__device__ __forceinline__ void mma_tf32(float* d, const uint32_t* a, const uint32_t* b)
{
    asm("mma.sync.aligned.m16n8k8.row.col.f32.tf32.tf32.f32 "
        "{%0,%1,%2,%3}, {%4,%5,%6,%7}, {%8,%9}, {%0,%1,%2,%3};"
        : "+f"(d[0]), "+f"(d[1]), "+f"(d[2]), "+f"(d[3])
        : "r"(a[0]), "r"(a[1]), "r"(a[2]), "r"(a[3]),
          "r"(b[0]), "r"(b[1]));
}

// bf16 mma.sync m16n8k16 (non-volatile)
__device__ __forceinline__ void mma_bf16(float* d, const uint32_t* a, uint32_t b0, uint32_t b1)
{
    asm("mma.sync.aligned.m16n8k16.row.col.f32.bf16.bf16.f32 "
        "{%0,%1,%2,%3}, {%4,%5,%6,%7}, {%8,%9}, {%0,%1,%2,%3};"
        : "+f"(d[0]), "+f"(d[1]), "+f"(d[2]), "+f"(d[3])
        : "r"(a[0]), "r"(a[1]), "r"(a[2]), "r"(a[3]),
          "r"(b0), "r"(b1));
}

// ---------------------------------------------------------------------------
// tf32 pre-conversion pass: x + 4 weight matrices, RNA-rounded once per call.
// ---------------------------------------------------------------------------
__global__ __launch_bounds__(256)
void cvt_tf32_kernel(const float* __restrict__ x,
                     const float* __restrict__ Wq, const float* __restrict__ Wk,
                     const float* __restrict__ Wv, const float* __restrict__ Wo)
{
    const int y = blockIdx.y;
    const float* src;
    float* dst;
    int n4;
    if (y == 0)      { src = x;  dst = g_xc;    n4 = BSZ * TSEQ * CDIM / 4; }
    else if (y == 1) { src = Wq; dst = g_Wc[0]; n4 = CDIM * CDIM / 4; }
    else if (y == 2) { src = Wk; dst = g_Wc[1]; n4 = CDIM * CDIM / 4; }
    else if (y == 3) { src = Wv; dst = g_Wc[2]; n4 = CDIM * CDIM / 4; }
    else             { src = Wo; dst = g_Wc[3]; n4 = CDIM * CDIM / 4; }

    const int i = blockIdx.x * blockDim.x + threadIdx.x;
    if (i < n4) {
        float4 v = ((const float4*)src)[i];
        v.x = to_tf32(v.x); v.y = to_tf32(v.y);
        v.z = to_tf32(v.z); v.w = to_tf32(v.w);
        ((float4*)dst)[i] = v;
    }
}

// ---------------------------------------------------------------------------
// Pack pass: bf16 hi/lo split of Q (qscale folded), K, and transposed V.
// Grid (T/64, B*H), 256 threads. Runs after the QKV GEMM.
// ---------------------------------------------------------------------------
__global__ __launch_bounds__(256)
void pack_kernel()
{
    __shared__ float sv[64][68];   // V tile [t][d]; 68: float4-aligned rows

    const int bh = blockIdx.y;
    const int t0 = blockIdx.x * 64;
    const int tid = threadIdx.x;
    const float qscale = 0.125f * 1.4426950408889634f;   // 1/sqrt(D)*log2(e)

    // load V tile [t0..t0+63][0..63] (coalesced float4)
#pragma unroll
    for (int i = 0; i < 4; ++i) {
        const int idx = tid + i * 256;        // 0..1023 float4 slots
        const int row = idx >> 4;
        const int c4  = (idx & 15) * 4;
        *(float4*)&sv[row][c4] =
            *(const float4*)&g_V[((size_t)bh * TSEQ + t0 + row) * DH + c4];
    }

    // Q and K: elementwise pair packing (no transpose)
#pragma unroll
    for (int i = 0; i < 8; ++i) {
        const int idx = tid + i * 256;        // 0..2047 (row, pair)
        const int row = idx >> 5;
        const int p   = idx & 31;
        const size_t src = ((size_t)bh * TSEQ + t0 + row) * DH + 2 * p;
        const size_t dst = ((size_t)bh * TSEQ + t0 + row) * (DH / 2) + p;

        float2 q = *(const float2*)&g_Q[src];
        q.x *= qscale; q.y *= qscale;
        uint32_t qh = pack_bf16x2(q.x, q.y);
        g_Qh[dst] = qh;
        g_Ql[dst] = pack_bf16x2(q.x - bf16lo_f(qh), q.y - bf16hi_f(qh));

        float2 k = *(const float2*)&g_K[src];
        uint32_t kh = pack_bf16x2(k.x, k.y);
        g_Kh[dst] = kh;
        g_Kl[dst] = pack_bf16x2(k.x - bf16lo_f(kh), k.y - bf16hi_f(kh));
    }
    __syncthreads();

    // V transposed: word(d, p) = pack(V[t0+2p][d], V[t0+2p+1][d])
#pragma unroll
    for (int i = 0; i < 8; ++i) {
        const int idx = tid + i * 256;        // 0..2047 (d, pair)
        const int d = idx >> 5;
        const int p = idx & 31;
        const float v0 = sv[2 * p][d];
        const float v1 = sv[2 * p + 1][d];
        const uint32_t h = pack_bf16x2(v0, v1);
        const size_t dst = ((size_t)bh * DH + d) * (TSEQ / 2) + t0 / 2 + p;
        g_Vh[dst] = h;
        g_Vl[dst] = pack_bf16x2(v0 - bf16lo_f(h), v1 - bf16hi_f(h));
    }
}

// ---------------------------------------------------------------------------
// tf32 tensor-core GEMM-NT, cp.async double-buffered, 2 CTAs/SM (proven R9).
// ---------------------------------------------------------------------------
#define GPAD 36
#define GEMM_SMEM (4 * 128 * GPAD * 4)   // 73728 B

template <int MODE, int NMAT>
__global__ __launch_bounds__(256, 2)
void gemm_mma_kernel(const float* __restrict__ A,
                     const float* __restrict__ W0, const float* __restrict__ W1,
                     const float* __restrict__ W2,
                     const float* __restrict__ b0, const float* __restrict__ b1,
                     const float* __restrict__ b2,
                     float* __restrict__ o0, float* __restrict__ o1,
                     float* __restrict__ o2)
{
    extern __shared__ float smem[];
    float (*As)[128][GPAD] = (float (*)[128][GPAD])(smem);
    float (*Bs)[128][GPAD] = (float (*)[128][GPAD])(smem + 2 * 128 * GPAD);
    const uint32_t smem_base = smem_u32(smem);

    const int z = (NMAT == 3) ? (int)blockIdx.z : 0;
    const float* __restrict__ W    = (z == 0) ? W0 : (z == 1 ? W1 : W2);
    const float* __restrict__ bias = (z == 0) ? b0 : (z == 1 ? b1 : b2);
    float* __restrict__ out        = (z == 0) ? o0 : (z == 1 ? o1 : o2);

    const int tid  = threadIdx.x;
    const int wid  = tid >> 5;
    const int lane = tid & 31;
    const int gID  = lane >> 2;
    const int tig  = lane & 3;
    const int n0 = blockIdx.x * 128;
    const int m0 = blockIdx.y * 128;
    const int wm = (wid >> 2) * 64;
    const int wn = (wid & 3) * 32;

    float acc[4][4][4];
#pragma unroll
    for (int mt = 0; mt < 4; ++mt)
#pragma unroll
        for (int nt = 0; nt < 4; ++nt)
#pragma unroll
            for (int r = 0; r < 4; ++r) acc[mt][nt][r] = 0.f;

    auto issue = [&](int buf, int k0) {
#pragma unroll
        for (int i = 0; i < 4; ++i) {
            const int idx = tid + i * 256;
            const int row = idx >> 3;
            const int q4  = (idx & 7) * 4;
            const uint32_t dA = smem_base +
                4u * (uint32_t)((buf * 128 + row) * GPAD + q4);
            const uint32_t dB = smem_base +
                4u * (uint32_t)(2 * 128 * GPAD + (buf * 128 + row) * GPAD + q4);
            cp_async16(dA, A + (size_t)(m0 + row) * CDIM + k0 + q4);
            cp_async16(dB, W + (size_t)(n0 + row) * CDIM + k0 + q4);
        }
        cp_commit();
    };

    issue(0, 0);

    for (int c = 0; c < 32; ++c) {
        const int cur = c & 1;
        if (c + 1 < 32) {
            issue(cur ^ 1, (c + 1) * 32);
            cp_wait<1>();
        } else {
            cp_wait<0>();
        }
        __syncthreads();

#pragma unroll
        for (int ks = 0; ks < 4; ++ks) {
            const int kk = ks * 8;
            uint32_t af[4][4];
#pragma unroll
            for (int mt = 0; mt < 4; ++mt) {
                const int r0 = wm + mt * 16 + gID;
                af[mt][0] = __float_as_uint(As[cur][r0    ][kk + tig    ]);
                af[mt][1] = __float_as_uint(As[cur][r0 + 8][kk + tig    ]);
                af[mt][2] = __float_as_uint(As[cur][r0    ][kk + tig + 4]);
                af[mt][3] = __float_as_uint(As[cur][r0 + 8][kk + tig + 4]);
            }
            uint32_t bf[4][2];
#pragma unroll
            for (int nt = 0; nt < 4; ++nt) {
                const int rn = wn + nt * 8 + gID;
                bf[nt][0] = __float_as_uint(Bs[cur][rn][kk + tig    ]);
                bf[nt][1] = __float_as_uint(Bs[cur][rn][kk + tig + 4]);
            }
#pragma unroll
            for (int mt = 0; mt < 4; ++mt)
#pragma unroll
                for (int nt = 0; nt < 4; ++nt)
                    mma_tf32(acc[mt][nt], af[mt], bf[nt]);
        }
        __syncthreads();
    }

#pragma unroll
    for (int mt = 0; mt < 4; ++mt) {
#pragma unroll
        for (int nt = 0; nt < 4; ++nt) {
            const int mrow0 = m0 + wm + mt * 16 + gID;
            const int mrow1 = mrow0 + 8;
            const int ncol  = n0 + wn + nt * 8 + 2 * tig;
            const float bx = bias[ncol], by = bias[ncol + 1];
            float2 v0, v1;
            v0.x = acc[mt][nt][0] + bx; v0.y = acc[mt][nt][1] + by;
            v1.x = acc[mt][nt][2] + bx; v1.y = acc[mt][nt][3] + by;
            if (MODE == 0) {
                *(float2*)&out[(size_t)mrow0 * CDIM + ncol] = v0;
                *(float2*)&out[(size_t)mrow1 * CDIM + ncol] = v1;
            } else {
                const int h  = ncol >> 6;
                const int dd = ncol & 63;
                const int b0r = mrow0 >> 11, t0r = mrow0 & (TSEQ - 1);
                const int b1r = mrow1 >> 11, t1r = mrow1 & (TSEQ - 1);
                *(float2*)&out[(((size_t)(b0r * HN + h)) * TSEQ + t0r) * DH + dd] = v0;
                *(float2*)&out[(((size_t)(b1r * HN + h)) * TSEQ + t1r) * DH + dd] = v1;
            }
        }
    }
}

// ----------------------------------------------------------------------------
// Tensor-core causal flash attention (bf16 split-3, ~fp32 accurate).
// Pre-packed K/V/Q; KV staging now DOUBLE-BUFFERED cp.async: tile kt+1's
// loads are in flight while tile kt computes. Dynamic smem 73.7 KB,
// 2 CTAs/SM. Block: 128 threads (4 warps). Q-tile 64, KV-tile 64.
// Grid: (T/64, B*H), bx reversed so heavy CTAs launch first.
// ----------------------------------------------------------------------------
#define KPAD 36
#define TILE_WORDS (64 * KPAD)                      // 2304 words per array
#define FLASH_SMEM (2 * 4 * TILE_WORDS * 4)         // 73728 B

__global__ __launch_bounds__(128)
void flash_attn_mma_kernel(float* __restrict__ att)
{
    extern __shared__ uint32_t fsm[];
    // layout: [buf][Khi,Klo,Vhi,Vlo][TILE_WORDS]
    const uint32_t fsm_base = smem_u32(fsm);

    const int bh  = blockIdx.y;
    const int bx  = gridDim.x - 1 - blockIdx.x;
    const int q0  = bx * 64;
    const int tid = threadIdx.x;
    const int wid = tid >> 5;
    const int lane = tid & 31;
    const int gID = lane >> 2;
    const int tig = lane & 3;

    const int rA = q0 + wid * 16 + gID;
    const int rB = rA + 8;

    // ---- Q fragments from packed buffers (qscale already folded)
    uint32_t qhi[4][4], qlo[4][4];
    {
        const uint32_t* QhA = g_Qh + ((size_t)bh * TSEQ + rA) * (DH / 2);
        const uint32_t* QhB = g_Qh + ((size_t)bh * TSEQ + rB) * (DH / 2);
        const uint32_t* QlA = g_Ql + ((size_t)bh * TSEQ + rA) * (DH / 2);
        const uint32_t* QlB = g_Ql + ((size_t)bh * TSEQ + rB) * (DH / 2);
#pragma unroll
        for (int ks = 0; ks < 4; ++ks) {
            const int p = 8 * ks + tig;
            qhi[ks][0] = QhA[p];     qhi[ks][1] = QhB[p];
            qhi[ks][2] = QhA[p + 4]; qhi[ks][3] = QhB[p + 4];
            qlo[ks][0] = QlA[p];     qlo[ks][1] = QlB[p];
            qlo[ks][2] = QlA[p + 4]; qlo[ks][3] = QlB[p + 4];
        }
    }

    // issue cp.async staging of KV tile `kb` into buffer `buf`
    auto stage = [&](int buf, int kbase) {
        const uint32_t base = fsm_base + 4u * (uint32_t)(buf * 4 * TILE_WORDS);
#pragma unroll
        for (int i = 0; i < 4; ++i) {
            const int idx = tid + i * 128;      // 0..511
            const int row = idx >> 3;           // 0..63 (key for K, d for V)
            const int c   = idx & 7;            // 16B chunk within row
            const uint32_t off = 4u * (uint32_t)(row * KPAD + c * 4);
            const size_t srcK = ((size_t)bh * TSEQ + kbase + row) * (DH / 2) + c * 4;
            const size_t srcV = ((size_t)bh * DH + row) * (TSEQ / 2) + kbase / 2 + c * 4;
            cp_async16(base + 0 * 4 * TILE_WORDS + off, g_Kh + srcK);
            cp_async16(base + 1 * 4 * TILE_WORDS + off, g_Kl + srcK);
            cp_async16(base + 2 * 4 * TILE_WORDS + off, g_Vh + srcV);
            cp_async16(base + 3 * 4 * TILE_WORDS + off, g_Vl + srcV);
        }
        cp_commit();
    };

    float O[8][4];
#pragma unroll
    for (int nt = 0; nt < 8; ++nt)
#pragma unroll
        for (int r = 0; r < 4; ++r) O[nt][r] = 0.f;
    float mA = -1e30f, mB = -1e30f, lA = 0.f, lB = 0.f;

    const int ntiles = bx + 1;

    stage(0, 0);   // prologue: tile 0 into buffer 0

    for (int kt = 0; kt < ntiles; ++kt) {
        const int cur = kt & 1;
        const int kbase = kt * 64;

        // all warps finished computing on buffer cur^1 (previous iteration)
        __syncthreads();
        if (kt + 1 < ntiles) {
            stage(cur ^ 1, kbase + 64);   // prefetch next tile
            cp_wait<1>();                 // buffer cur complete (own copies)
        } else {
            cp_wait<0>();
        }
        __syncthreads();                  // everyone's copies for cur visible

        const uint32_t* sKhi = fsm + (cur * 4 + 0) * TILE_WORDS;
        const uint32_t* sKlo = fsm + (cur * 4 + 1) * TILE_WORDS;
        const uint32_t* sVhi = fsm + (cur * 4 + 2) * TILE_WORDS;
        const uint32_t* sVlo = fsm + (cur * 4 + 3) * TILE_WORDS;

        // ---- QK^T: S[16 x 64] per warp
        float S[8][4];
#pragma unroll
        for (int nt = 0; nt < 8; ++nt) {
            float c[4] = {0.f, 0.f, 0.f, 0.f};
            const uint32_t* rh = &sKhi[(8 * nt + gID) * KPAD];
            const uint32_t* rl = &sKlo[(8 * nt + gID) * KPAD];
#pragma unroll
            for (int ks = 0; ks < 4; ++ks) {
                const uint32_t b0h = rh[8 * ks + tig];
                const uint32_t b1h = rh[8 * ks + 4 + tig];
                const uint32_t b0l = rl[8 * ks + tig];
                const uint32_t b1l = rl[8 * ks + 4 + tig];
                mma_bf16(c, qhi[ks], b0h, b1h);
                mma_bf16(c, qhi[ks], b0l, b1l);
                mma_bf16(c, qlo[ks], b0h, b1h);
            }
            S[nt][0] = c[0]; S[nt][1] = c[1]; S[nt][2] = c[2]; S[nt][3] = c[3];
        }

        // ---- causal mask on the diagonal tile
        if (kt == bx) {
#pragma unroll
            for (int nt = 0; nt < 8; ++nt) {
                const int col = kbase + 8 * nt + 2 * tig;
                if (col     > rA) S[nt][0] = -1e30f;
                if (col + 1 > rA) S[nt][1] = -1e30f;
                if (col     > rB) S[nt][2] = -1e30f;
                if (col + 1 > rB) S[nt][3] = -1e30f;
            }
        }

        // ---- online softmax (log2 domain)
        float tmA = -1e30f, tmB = -1e30f;
#pragma unroll
        for (int nt = 0; nt < 8; ++nt) {
            tmA = fmaxf(tmA, fmaxf(S[nt][0], S[nt][1]));
            tmB = fmaxf(tmB, fmaxf(S[nt][2], S[nt][3]));
        }
        tmA = fmaxf(tmA, __shfl_xor_sync(0xffffffffu, tmA, 1));
        tmA = fmaxf(tmA, __shfl_xor_sync(0xffffffffu, tmA, 2));
        tmB = fmaxf(tmB, __shfl_xor_sync(0xffffffffu, tmB, 1));
        tmB = fmaxf(tmB, __shfl_xor_sync(0xffffffffu, tmB, 2));

        const float nmA = fmaxf(mA, tmA);
        const float nmB = fmaxf(mB, tmB);
        const float corrA = fast_exp2(mA - nmA);
        const float corrB = fast_exp2(mB - nmB);
        mA = nmA; mB = nmB;
        lA *= corrA; lB *= corrB;
#pragma unroll
        for (int nt = 0; nt < 8; ++nt) {
            O[nt][0] *= corrA; O[nt][1] *= corrA;
            O[nt][2] *= corrB; O[nt][3] *= corrB;
        }

        uint32_t ph[8][2], pl[8][2];
        float sA = 0.f, sB = 0.f;
#pragma unroll
        for (int nt = 0; nt < 8; ++nt) {
            const float p0 = fast_exp2(S[nt][0] - nmA);
            const float p1 = fast_exp2(S[nt][1] - nmA);
            const float p2 = fast_exp2(S[nt][2] - nmB);
            const float p3 = fast_exp2(S[nt][3] - nmB);
            sA += p0 + p1; sB += p2 + p3;
            uint32_t h;
            h = pack_bf16x2(p0, p1); ph[nt][0] = h;
            pl[nt][0] = pack_bf16x2(p0 - bf16lo_f(h), p1 - bf16hi_f(h));
            h = pack_bf16x2(p2, p3); ph[nt][1] = h;
            pl[nt][1] = pack_bf16x2(p2 - bf16lo_f(h), p3 - bf16hi_f(h));
        }
        sA += __shfl_xor_sync(0xffffffffu, sA, 1);
        sA += __shfl_xor_sync(0xffffffffu, sA, 2);
        sB += __shfl_xor_sync(0xffffffffu, sB, 1);
        sB += __shfl_xor_sync(0xffffffffu, sB, 2);
        lA += sA; lB += sB;

        // ---- PV: O += P @ V
#pragma unroll
        for (int dnt = 0; dnt < 8; ++dnt) {
            const uint32_t* rh = &sVhi[(8 * dnt + gID) * KPAD];
            const uint32_t* rl = &sVlo[(8 * dnt + gID) * KPAD];
#pragma unroll
            for (int ks = 0; ks < 4; ++ks) {
                uint32_t ah[4] = {ph[2 * ks][0], ph[2 * ks][1],
                                  ph[2 * ks + 1][0], ph[2 * ks + 1][1]};
                uint32_t al[4] = {pl[2 * ks][0], pl[2 * ks][1],
                                  pl[2 * ks + 1][0], pl[2 * ks + 1][1]};
                const uint32_t b0h = rh[8 * ks + tig];
                const uint32_t b1h = rh[8 * ks + 4 + tig];
                const uint32_t b0l = rl[8 * ks + tig];
                const uint32_t b1l = rl[8 * ks + 4 + tig];
                mma_bf16(O[dnt], ah, b0h, b1h);
                mma_bf16(O[dnt], ah, b0l, b1l);
                mma_bf16(O[dnt], al, b0h, b1h);
            }
        }
    }

    // ---- epilogue: normalize, tf32-round, store to [B,T,C]
    const float invA = 1.0f / lA;
    const float invB = 1.0f / lB;
    const int b = bh >> 4;
    const int h = bh & 15;
    float* oA = att + ((size_t)(b * TSEQ + rA)) * CDIM + h * DH;
    float* oB = att + ((size_t)(b * TSEQ + rB)) * CDIM + h * DH;
#pragma unroll
    for (int nt = 0; nt < 8; ++nt) {
        const int col = 8 * nt + 2 * tig;
        float2 vA, vB;
        vA.x = to_tf32(O[nt][0] * invA); vA.y = to_tf32(O[nt][1] * invA);
        vB.x = to_tf32(O[nt][2] * invB); vB.y = to_tf32(O[nt][3] * invB);
        *(float2*)(oA + col) = vA;
        *(float2*)(oB + col) = vB;
    }
}

// ----------------------------------------------------------------------------
extern "C" void kernel_launch(void* const* d_in, const int* in_sizes, int n_in,
                              void* d_out, int out_size)
{
    const float* x  = (const float*)d_in[0];
    const float* Wq = (const float*)d_in[1];
    const float* bq = (const float*)d_in[2];
    const float* Wk = (const float*)d_in[3];
    const float* bk = (const float*)d_in[4];
    const float* Wv = (const float*)d_in[5];
    const float* bv = (const float*)d_in[6];
    const float* Wo = (const float*)d_in[7];
    const float* bo = (const float*)d_in[8];
    float* out = (float*)d_out;

    float *Qp, *Kp, *Vp, *Ap, *xc, *wc;
    cudaGetSymbolAddress((void**)&Qp, g_Q);
    cudaGetSymbolAddress((void**)&Kp, g_K);
    cudaGetSymbolAddress((void**)&Vp, g_V);
    cudaGetSymbolAddress((void**)&Ap, g_att);
    cudaGetSymbolAddress((void**)&xc, g_xc);
    cudaGetSymbolAddress((void**)&wc, g_Wc);
    float* Wqc = wc;
    float* Wkc = wc + (size_t)CDIM * CDIM;
    float* Wvc = wc + 2 * (size_t)CDIM * CDIM;
    float* Woc = wc + 3 * (size_t)CDIM * CDIM;

    cudaFuncSetAttribute(gemm_mma_kernel<1, 3>,
                         cudaFuncAttributeMaxDynamicSharedMemorySize, GEMM_SMEM);
    cudaFuncSetAttribute(gemm_mma_kernel<0, 1>,
                         cudaFuncAttributeMaxDynamicSharedMemorySize, GEMM_SMEM);
    cudaFuncSetAttribute(flash_attn_mma_kernel,
                         cudaFuncAttributeMaxDynamicSharedMemorySize, FLASH_SMEM);

    // tf32 pre-rounding of x and all weights
    dim3 cvt_grid((BSZ * TSEQ * CDIM / 4 + 255) / 256, 5);
    cvt_tf32_kernel<<<cvt_grid, 256>>>(x, Wq, Wk, Wv, Wo);

    // fused Q/K/V projections
    dim3 qkv_grid(CDIM / 128, (BSZ * TSEQ) / 128, 3);
    gemm_mma_kernel<1, 3><<<qkv_grid, 256, GEMM_SMEM>>>(
        xc, Wqc, Wkc, Wvc, bq, bk, bv, Qp, Kp, Vp);

    // bf16 hi/lo pack of Q (scaled), K, V (transposed)
    dim3 pack_grid(TSEQ / 64, BSZ * HN);
    pack_kernel<<<pack_grid, 256>>>();

    // tensor-core flash attention (double-buffered KV pipeline)
    dim3 attn_grid(TSEQ / 64, BSZ * HN);              // (32, 32)
    flash_attn_mma_kernel<<<attn_grid, 128, FLASH_SMEM>>>(Ap);

    // output projection
    dim3 o_grid(CDIM / 128, (BSZ * TSEQ) / 128, 1);
    gemm_mma_kernel<0, 1><<<o_grid, 256, GEMM_SMEM>>>(
        Ap, Woc, Woc, Woc, bo, bo, bo, out, out, out);
}